// round 1
// baseline (speedup 1.0000x reference)
#include <cuda_runtime.h>
#include <cstdint>

#define NN   8192
#define FIN  256
#define FOUT 64
#define RI   32
#define TJ   128

// Scratch (no cudaMalloc allowed)
__device__ __align__(16) float g_Wh[NN * FOUT];
__device__ float g_s1[NN];
__device__ float g_s2[NN];

// ---------------------------------------------------------------------------
// Kernel 1: Wh = h @ W  (8192x256 @ 256x64), s1 = Wh@a1, s2 = Wh@a2
// block: 256 threads = 64 k-lanes x 4 row-groups; 16 rows per block
// ---------------------------------------------------------------------------
__global__ __launch_bounds__(256) void k_prep(const float* __restrict__ h,
                                              const float* __restrict__ W,
                                              const float* __restrict__ a) {
    __shared__ float hS[16 * FIN];          // 16 KB
    __shared__ float redS[2][8][4];         // [s1/s2][warp][rr]
    int t  = threadIdx.x;
    int k  = t & 63;
    int rg = t >> 6;
    int rowBase = blockIdx.x * 16;
    const float* hb = h + (size_t)rowBase * FIN;

    #pragma unroll
    for (int p = 0; p < 16; p++) hS[p * 256 + t] = hb[p * 256 + t];
    __syncthreads();

    float acc[4] = {0.f, 0.f, 0.f, 0.f};
    for (int c = 0; c < FIN; c++) {
        float wv = W[c * FOUT + k];
        #pragma unroll
        for (int rr = 0; rr < 4; rr++)
            acc[rr] = fmaf(hS[(rg * 4 + rr) * FIN + c], wv, acc[rr]);
    }

    float a1v = a[k];
    float a2v = a[FOUT + k];
    int wid = t >> 5;
    #pragma unroll
    for (int rr = 0; rr < 4; rr++) {
        int row = rowBase + rg * 4 + rr;
        g_Wh[row * FOUT + k] = acc[rr];
        float p1 = acc[rr] * a1v;
        float p2 = acc[rr] * a2v;
        #pragma unroll
        for (int o = 16; o > 0; o >>= 1) {
            p1 += __shfl_down_sync(0xffffffffu, p1, o);
            p2 += __shfl_down_sync(0xffffffffu, p2, o);
        }
        if ((t & 31) == 0) { redS[0][wid][rr] = p1; redS[1][wid][rr] = p2; }
    }
    __syncthreads();
    if (k < 4) {
        int rr  = k;
        int row = rowBase + rg * 4 + rr;
        g_s1[row] = redS[0][2 * rg][rr] + redS[0][2 * rg + 1][rr];
        g_s2[row] = redS[1][2 * rg][rr] + redS[1][2 * rg + 1][rr];
    }
}

// ---------------------------------------------------------------------------
// Kernel 2: fused masked-softmax aggregation (no max-subtraction needed:
// |s1+s2| bounded, exp never overflows in fp32; softmax = Num/Z, both linear)
//   Phase A: w[i][jj] = adj ? exp(lrelu(s1[i]+s2[j])) : 0   -> SMEM (+Z)
//   Phase B: acc[i][k] += w * Wh[j][k]  via packed fma.rn.f32x2
// block: 256 threads, RI=32 rows, j tiled by TJ=128
// ---------------------------------------------------------------------------
__global__ __launch_bounds__(256) void k_main(const int* __restrict__ adj,
                                              float* __restrict__ out) {
    __shared__ float wS[RI][TJ + 1];   // +1 pad: conflict-free STS/LDS
    __shared__ float s1S[RI];
    __shared__ float zS[RI];
    int t  = threadIdx.x;
    int i0 = blockIdx.x * RI;

    if (t < RI) s1S[t] = g_s1[i0 + t];
    __syncthreads();

    // Phase A mapping: 8 threads per row
    int rowA = t >> 3;
    int tj   = t & 7;
    float s1v = s1S[rowA];
    const int* adjRow = adj + (size_t)(i0 + rowA) * NN;
    float zp = 0.f;

    // Phase B mapping: 16 k4-lanes x 16 row-groups (2 rows each)
    int k4 = t & 15;
    int rg = t >> 4;
    const ulonglong2* Wh2 = reinterpret_cast<const ulonglong2*>(g_Wh);
    unsigned long long accA0 = 0ull, accB0 = 0ull;   // row 2rg,   k4*4 .. +3
    unsigned long long accA1 = 0ull, accB1 = 0ull;   // row 2rg+1, k4*4 .. +3

    for (int tile = 0; tile < NN / TJ; tile++) {
        int j0 = tile * TJ;

        // ---- Phase A: weights ----
        #pragma unroll
        for (int q = 0; q < TJ / 8; q++) {
            int jj = tj + (q << 3);
            int j  = j0 + jj;
            int av = adjRow[j];
            float x = s1v + __ldg(&g_s2[j]);
            float e = (x > 0.f) ? x : 0.2f * x;
            float w = (av > 0) ? __expf(e) : 0.f;
            wS[rowA][jj] = w;
            zp += w;
        }
        __syncthreads();

        // ---- Phase B: packed-f32x2 accumulation ----
        #pragma unroll 4
        for (int jj = 0; jj < TJ; jj++) {
            int j = j0 + jj;
            ulonglong2 wh = Wh2[(size_t)j * 16 + k4];
            float w0 = wS[2 * rg + 0][jj];
            float w1 = wS[2 * rg + 1][jj];
            unsigned long long w0p, w1p;
            asm("mov.b64 %0, {%1, %1};" : "=l"(w0p) : "f"(w0));
            asm("mov.b64 %0, {%1, %1};" : "=l"(w1p) : "f"(w1));
            asm("fma.rn.f32x2 %0, %1, %2, %0;" : "+l"(accA0) : "l"(w0p), "l"(wh.x));
            asm("fma.rn.f32x2 %0, %1, %2, %0;" : "+l"(accB0) : "l"(w0p), "l"(wh.y));
            asm("fma.rn.f32x2 %0, %1, %2, %0;" : "+l"(accA1) : "l"(w1p), "l"(wh.x));
            asm("fma.rn.f32x2 %0, %1, %2, %0;" : "+l"(accB1) : "l"(w1p), "l"(wh.y));
        }
        __syncthreads();
    }

    // ---- Z reduction (8 lanes per row, within warp) ----
    #pragma unroll
    for (int o = 4; o > 0; o >>= 1)
        zp += __shfl_down_sync(0xffffffffu, zp, o, 8);
    if (tj == 0) zS[rowA] = zp;
    __syncthreads();

    // ---- Epilogue: divide by Z, ELU, store ----
    #pragma unroll
    for (int r = 0; r < 2; r++) {
        int row = 2 * rg + r;
        float invz = 1.0f / zS[row];
        unsigned long long pa = (r == 0) ? accA0 : accA1;
        unsigned long long pb = (r == 0) ? accB0 : accB1;
        float v0, v1, v2, v3;
        asm("mov.b64 {%0, %1}, %2;" : "=f"(v0), "=f"(v1) : "l"(pa));
        asm("mov.b64 {%0, %1}, %2;" : "=f"(v2), "=f"(v3) : "l"(pb));
        float o0 = v0 * invz, o1 = v1 * invz, o2 = v2 * invz, o3 = v3 * invz;
        o0 = (o0 > 0.f) ? o0 : expm1f(o0);
        o1 = (o1 > 0.f) ? o1 : expm1f(o1);
        o2 = (o2 > 0.f) ? o2 : expm1f(o2);
        o3 = (o3 > 0.f) ? o3 : expm1f(o3);
        float4 ov = make_float4(o0, o1, o2, o3);
        reinterpret_cast<float4*>(out)[(size_t)(i0 + row) * (FOUT / 4) + k4] = ov;
    }
}

// ---------------------------------------------------------------------------
extern "C" void kernel_launch(void* const* d_in, const int* in_sizes, int n_in,
                              void* d_out, int out_size) {
    const float* h   = (const float*)d_in[0];
    const int*   adj = (const int*)  d_in[1];
    const float* W   = (const float*)d_in[2];
    const float* a   = (const float*)d_in[3];
    float* out = (float*)d_out;

    k_prep<<<NN / 16, 256>>>(h, W, a);
    k_main<<<NN / RI, 256>>>(adj, out);
}

// round 3
// speedup vs baseline: 6.0437x; 6.0437x over previous
#include <cuda_runtime.h>
#include <cstdint>

#define NN   8192
#define FIN  256
#define FOUT 64
#define RI   32
#define TJ   128

typedef unsigned long long ull;

// Scratch (no cudaMalloc allowed)
__device__ __align__(16) float g_Wh[NN * FOUT];
__device__ float g_s1[NN];
__device__ __align__(16) float g_s2[NN];

// dynamic smem layout (bytes)
#define OFF_LO   0          // Wh lo-half: 128 j * 128B  = 16384
#define OFF_HI   16384      // Wh hi-half: 16384
#define OFF_WD   32768      // dup'd weights: 128 jj * 272B = 34816
#define WD_STRIDE 272
#define OFF_S1   67584      // 32 floats
#define OFF_Z    67712      // 32 floats
#define SMEM_BYTES 67840

__device__ __forceinline__ void fma2(ull& acc, ull a, ull b) {
    asm("fma.rn.f32x2 %0, %1, %2, %0;" : "+l"(acc) : "l"(a), "l"(b));
}

// ---------------------------------------------------------------------------
// Kernel 1: Wh = h @ W, s1 = Wh@a1, s2 = Wh@a2   (~12us)
// ---------------------------------------------------------------------------
__global__ __launch_bounds__(256) void k_prep(const float* __restrict__ h,
                                              const float* __restrict__ W,
                                              const float* __restrict__ a) {
    __shared__ float hS[16 * FIN];
    __shared__ float redS[2][8][4];
    int t  = threadIdx.x;
    int k  = t & 63;
    int rg = t >> 6;
    int rowBase = blockIdx.x * 16;
    const float* hb = h + (size_t)rowBase * FIN;

    #pragma unroll
    for (int p = 0; p < 16; p++) hS[p * 256 + t] = hb[p * 256 + t];
    __syncthreads();

    float acc[4] = {0.f, 0.f, 0.f, 0.f};
    for (int c = 0; c < FIN; c++) {
        float wv = W[c * FOUT + k];
        #pragma unroll
        for (int rr = 0; rr < 4; rr++)
            acc[rr] = fmaf(hS[(rg * 4 + rr) * FIN + c], wv, acc[rr]);
    }

    float a1v = a[k];
    float a2v = a[FOUT + k];
    int wid = t >> 5;
    #pragma unroll
    for (int rr = 0; rr < 4; rr++) {
        int row = rowBase + rg * 4 + rr;
        g_Wh[row * FOUT + k] = acc[rr];
        float p1 = acc[rr] * a1v;
        float p2 = acc[rr] * a2v;
        #pragma unroll
        for (int o = 16; o > 0; o >>= 1) {
            p1 += __shfl_down_sync(0xffffffffu, p1, o);
            p2 += __shfl_down_sync(0xffffffffu, p2, o);
        }
        if ((t & 31) == 0) { redS[0][wid][rr] = p1; redS[1][wid][rr] = p2; }
    }
    __syncthreads();
    if (k < 4) {
        int rr  = k;
        int row = rowBase + rg * 4 + rr;
        g_s1[row] = redS[0][2 * rg][rr] + redS[0][2 * rg + 1][rr];
        g_s2[row] = redS[1][2 * rg][rr] + redS[1][2 * rg + 1][rr];
    }
}

// ---------------------------------------------------------------------------
// Kernel 2: fused masked-softmax aggregation, all-SMEM hot loop.
//   Phase A: w = adj ? exp(lrelu(s1+s2)) : 0  -> SMEM as {w,w} pairs (+Z)
//            + cooperative staging of Wh tile into SMEM (lo/hi split)
//   Phase B: acc{k,k+1} += {w,w} * {wh_k,wh_k+1}  (4 LDS.128 + 16 FFMA2 / jj)
// thread map (256 thr): k8 = t&7 (8 k-floats), r0 = ((t>>3)&7)*4 (4 rows),
//                       jsub = t>>6 (4-way jj split, reduced at end)
// ---------------------------------------------------------------------------
__global__ __launch_bounds__(256, 3) void k_main(const int* __restrict__ adj,
                                                 float* __restrict__ out) {
    extern __shared__ char smx[];
    float* whLo = (float*)(smx + OFF_LO);
    float* whHi = (float*)(smx + OFF_HI);
    char*  wd   = smx + OFF_WD;
    float* s1S  = (float*)(smx + OFF_S1);
    float* zS   = (float*)(smx + OFF_Z);

    int t  = threadIdx.x;
    int i0 = blockIdx.x * RI;
    if (t < RI) s1S[t] = g_s1[i0 + t];
    __syncthreads();

    // Phase A ids: 8 threads per row
    int rowA = t >> 3;
    int tj   = t & 7;
    float s1v = s1S[rowA];
    const int4* adjR = (const int4*)(adj + (size_t)(i0 + rowA) * NN);
    float zp = 0.f;

    // Phase B ids
    int k8    = t & 7;
    int rgAll = t >> 3;
    int r0    = (rgAll & 7) * 4;
    int jsub  = rgAll >> 3;
    int mBase = jsub * 32;

    ull acc[4][4];
    #pragma unroll
    for (int r = 0; r < 4; r++)
        #pragma unroll
        for (int kp = 0; kp < 4; kp++) acc[r][kp] = 0ull;

    // prefetch tile 0 adj
    int4 pa[4];
    #pragma unroll
    for (int q = 0; q < 4; q++) pa[q] = adjR[q * 8 + tj];

    for (int tile = 0; tile < NN / TJ; tile++) {
        int j0 = tile * TJ;

        // ---- stage Wh tile (lo/hi split: conflict-free LDS.128 in Phase B) ----
        #pragma unroll
        for (int p = 0; p < 8; p++) {
            int fid = t + 256 * p;
            int j  = fid >> 4;
            int g4 = fid & 15;
            float4 v = *(const float4*)(g_Wh + (size_t)(j0 + j) * FOUT + g4 * 4);
            float* dst = (g4 & 1) ? whHi : whLo;
            *(float4*)(dst + j * 32 + (g4 >> 1) * 4) = v;
        }

        // ---- Phase A: weights, duplicated pairs ----
        #pragma unroll
        for (int q = 0; q < 4; q++) {
            int v   = q * 8 + tj;
            int jj0 = v * 4;
            float4 s2v = *(const float4*)(g_s2 + j0 + jj0);
            int   am[4] = {pa[q].x, pa[q].y, pa[q].z, pa[q].w};
            float sv[4] = {s2v.x, s2v.y, s2v.z, s2v.w};
            #pragma unroll
            for (int c = 0; c < 4; c++) {
                float x = s1v + sv[c];
                float e = (x > 0.f) ? x : 0.2f * x;
                float w = (am[c] > 0) ? __expf(e) : 0.f;
                zp += w;
                *(float2*)(wd + (jj0 + c) * WD_STRIDE + rowA * 8) = make_float2(w, w);
            }
        }

        // ---- prefetch next tile's adj (hides DRAM latency under Phase B) ----
        if (tile < NN / TJ - 1) {
            const int4* nxt = (const int4*)(adj + (size_t)(i0 + rowA) * NN + j0 + TJ);
            #pragma unroll
            for (int q = 0; q < 4; q++) pa[q] = nxt[q * 8 + tj];
        }
        __syncthreads();

        // ---- Phase B: pure SMEM + FFMA2 ----
        #pragma unroll 4
        for (int m = 0; m < 32; m++) {
            int jj = mBase + m;
            const float* lb = whLo + jj * 32 + k8 * 4;
            const float* hb = whHi + jj * 32 + k8 * 4;
            ulonglong2 wl  = *(const ulonglong2*)lb;   // pairs {k0,k1},{k2,k3}
            ulonglong2 wh_ = *(const ulonglong2*)hb;   // pairs {k4,k5},{k6,k7}
            const char* wb = wd + jj * WD_STRIDE + r0 * 8;
            ulonglong2 w01 = *(const ulonglong2*)wb;        // {w_r0,w_r0},{w_r1,w_r1}
            ulonglong2 w23 = *(const ulonglong2*)(wb + 16); // {w_r2,w_r2},{w_r3,w_r3}
            fma2(acc[0][0], w01.x, wl.x);  fma2(acc[0][1], w01.x, wl.y);
            fma2(acc[0][2], w01.x, wh_.x); fma2(acc[0][3], w01.x, wh_.y);
            fma2(acc[1][0], w01.y, wl.x);  fma2(acc[1][1], w01.y, wl.y);
            fma2(acc[1][2], w01.y, wh_.x); fma2(acc[1][3], w01.y, wh_.y);
            fma2(acc[2][0], w23.x, wl.x);  fma2(acc[2][1], w23.x, wl.y);
            fma2(acc[2][2], w23.x, wh_.x); fma2(acc[2][3], w23.x, wh_.y);
            fma2(acc[3][0], w23.y, wl.x);  fma2(acc[3][1], w23.y, wl.y);
            fma2(acc[3][2], w23.y, wh_.x); fma2(acc[3][3], w23.y, wh_.y);
        }
        __syncthreads();
    }

    // ---- Z reduction (8 lanes per row) ----
    #pragma unroll
    for (int o = 4; o > 0; o >>= 1)
        zp += __shfl_down_sync(0xffffffffu, zp, o, 8);
    if (tj == 0) zS[rowA] = zp;
    __syncthreads();

    // ---- cross-jsub reduction in SMEM (packed adds), then epilogue ----
    ull* scratch = (ull*)smx;            // reuse lo/hi region (24KB needed)
    int t63 = t & 63;
    if (jsub > 0) {
        ull* dst = scratch + ((jsub - 1) * 64 + t63) * 16;
        #pragma unroll
        for (int r = 0; r < 4; r++)
            #pragma unroll
            for (int kp = 0; kp < 4; kp++) dst[r * 4 + kp] = acc[r][kp];
    }
    __syncthreads();
    if (jsub == 0) {
        #pragma unroll
        for (int s = 0; s < 3; s++) {
            const ull* src = scratch + (s * 64 + t63) * 16;
            #pragma unroll
            for (int r = 0; r < 4; r++)
                #pragma unroll
                for (int kp = 0; kp < 4; kp++) {
                    ull p = src[r * 4 + kp];
                    asm("add.rn.f32x2 %0, %0, %1;" : "+l"(acc[r][kp]) : "l"(p));
                }
        }
        // per-row serial epilogue (keeps peak register pressure low)
        for (int r = 0; r < 4; r++) {
            int row = r0 + r;
            float invz = 1.0f / zS[row];
            float o8[8];
            #pragma unroll
            for (int kp = 0; kp < 4; kp++) {
                float lo_, hi_;
                asm("mov.b64 {%0,%1}, %2;" : "=f"(lo_), "=f"(hi_) : "l"(acc[r][kp]));
                o8[kp * 2]     = lo_;
                o8[kp * 2 + 1] = hi_;
            }
            #pragma unroll
            for (int c = 0; c < 8; c++) {
                float v = o8[c] * invz;
                o8[c] = (v > 0.f) ? v : expm1f(v);
            }
            float4* ob = (float4*)(out + (size_t)(i0 + row) * FOUT + k8 * 8);
            ob[0] = make_float4(o8[0], o8[1], o8[2], o8[3]);
            ob[1] = make_float4(o8[4], o8[5], o8[6], o8[7]);
        }
    }
}

// ---------------------------------------------------------------------------
extern "C" void kernel_launch(void* const* d_in, const int* in_sizes, int n_in,
                              void* d_out, int out_size) {
    const float* h   = (const float*)d_in[0];
    const int*   adj = (const int*)  d_in[1];
    const float* W   = (const float*)d_in[2];
    const float* a   = (const float*)d_in[3];
    float* out = (float*)d_out;

    cudaFuncSetAttribute(k_main, cudaFuncAttributeMaxDynamicSharedMemorySize,
                         SMEM_BYTES);
    k_prep<<<NN / 16, 256>>>(h, W, a);
    k_main<<<NN / RI, 256, SMEM_BYTES>>>(adj, out);
}

// round 9
// speedup vs baseline: 14.8614x; 2.4590x over previous
#include <cuda_runtime.h>
#include <cuda_fp16.h>
#include <cstdint>

#define NN    8192
#define FIN   256
#define FOUT  64
#define RT    128
#define NBLK  128

typedef unsigned int u32;

// ---- global scratch (no cudaMalloc allowed) ----
__device__ float g_s1[NN];
__device__ __align__(16) float g_s2[NN];
__device__ __align__(16) __half g_Wh_hi[NN * FOUT];   // [j][f] row-major
__device__ __align__(16) __half g_Wh_lo[NN * FOUT];
__device__ __align__(16) float g_Dp[NBLK * RT * FOUT];
__device__ float g_Zp[NBLK * RT];

static __device__ __forceinline__ u32 smem_u32(const void* p) {
    u32 a;
    asm("{ .reg .u64 t; cvta.to.shared.u64 t, %1; cvt.u32.u64 %0, t; }" : "=r"(a) : "l"(p));
    return a;
}

#define MMA(d, a, b0_, b1_)                                                     \
    asm volatile("mma.sync.aligned.m16n8k16.row.col.f32.f16.f16.f32 "           \
        "{%0,%1,%2,%3}, {%4,%5,%6,%7}, {%8,%9}, {%0,%1,%2,%3};"                 \
        : "+f"(d[0]), "+f"(d[1]), "+f"(d[2]), "+f"(d[3])                        \
        : "r"(a[0]), "r"(a[1]), "r"(a[2]), "r"(a[3]), "r"(b0_), "r"(b1_))

// ---------------------------------------------------------------------------
// Kernel 1: Wh = h@W ; s1 = Wh@a1 ; s2 = Wh@a2 ; fp16 hi/lo split of Wh
// ---------------------------------------------------------------------------
__global__ __launch_bounds__(256) void k_prep(const float* __restrict__ h,
                                              const float* __restrict__ W,
                                              const float* __restrict__ a) {
    __shared__ float hS[16 * FIN];
    __shared__ float redS[2][8][4];
    int t  = threadIdx.x;
    int k  = t & 63;
    int rg = t >> 6;
    int rowBase = blockIdx.x * 16;
    const float* hb = h + (size_t)rowBase * FIN;

    #pragma unroll
    for (int p = 0; p < 16; p++) hS[p * 256 + t] = hb[p * 256 + t];
    __syncthreads();

    float acc[4] = {0.f, 0.f, 0.f, 0.f};
    for (int c = 0; c < FIN; c++) {
        float wv = W[c * FOUT + k];
        #pragma unroll
        for (int rr = 0; rr < 4; rr++)
            acc[rr] = fmaf(hS[(rg * 4 + rr) * FIN + c], wv, acc[rr]);
    }

    float a1v = a[k];
    float a2v = a[FOUT + k];
    int wid = t >> 5;
    #pragma unroll
    for (int rr = 0; rr < 4; rr++) {
        int j = rowBase + rg * 4 + rr;
        __half hv = __float2half(acc[rr]);
        float hf  = __half2float(hv);
        __half lv = __float2half(acc[rr] - hf);
        g_Wh_hi[j * FOUT + k] = hv;
        g_Wh_lo[j * FOUT + k] = lv;

        float p1 = acc[rr] * a1v;
        float p2 = acc[rr] * a2v;
        #pragma unroll
        for (int o = 16; o > 0; o >>= 1) {
            p1 += __shfl_down_sync(0xffffffffu, p1, o);
            p2 += __shfl_down_sync(0xffffffffu, p2, o);
        }
        if ((t & 31) == 0) { redS[0][wid][rr] = p1; redS[1][wid][rr] = p2; }
    }
    __syncthreads();
    if (k < 4) {
        int rr  = k;
        int row = rowBase + rg * 4 + rr;
        g_s1[row] = redS[0][2 * rg][rr] + redS[0][2 * rg + 1][rr];
        g_s2[row] = redS[1][2 * rg][rr] + redS[1][2 * rg + 1][rr];
    }
}

// ---------------------------------------------------------------------------
// Kernel 2: mma.sync flash-GAT. Block (rt,jh): 128 rows x 4096 j.
// 8 warps = 8 m-tiles of 16 rows. K loop: 256 k-steps of 16 j,
// staged as 64 subtiles of 64 j. fp16-split, 3 MMA passes, w scaled 2^-8.
// ---------------------------------------------------------------------------
__global__ __launch_bounds__(256) void k_main(const int* __restrict__ adj) {
    __shared__ float s2S[4096];                       // 16 KB
    __shared__ __align__(16) char whH[64 * 144];      // 9216 B (144B padded rows)
    __shared__ __align__(16) char whL[64 * 144];

    int t = threadIdx.x, lane = t & 31, wid = t >> 5;
    int blk = blockIdx.x;
    int i0 = (blk >> 1) * RT;
    int jb = (blk & 1) * 4096;
    int g = lane >> 2, tc = lane & 3;

    #pragma unroll
    for (int q = 0; q < 16; q++) s2S[t + q * 256] = g_s2[jb + t + q * 256];

    int row0 = i0 + wid * 16 + g;
    float s1v0 = g_s1[row0], s1v1 = g_s1[row0 + 8];
    const int* aR0 = adj + (size_t)row0 * NN + jb;
    const int* aR1 = aR0 + (size_t)8 * NN;

    float D[8][4];
    #pragma unroll
    for (int n = 0; n < 8; n++) { D[n][0] = D[n][1] = D[n][2] = D[n][3] = 0.f; }
    float z0 = 0.f, z1 = 0.f;

    u32 whHb = smem_u32(whH), whLb = smem_u32(whL);
    // ldmatrix.x4 lane address: matrix m = lane>>3 -> (khalf = m&1, n-sub = m>>1)
    int laneoff = (((lane >> 3) & 1) * 8 + (lane & 7)) * 144 + (lane >> 4) * 16;

    int sj0 = t >> 3, sc = t & 7;   // staging: chunk fid=t -> row sj0, 16B chunk sc
    const int4* gH = (const int4*)g_Wh_hi;  // int4 idx = j*8 + c
    const int4* gL = (const int4*)g_Wh_lo;

    // ---- prefetch subtile 0: Wh + adj ----
    int4 ph0 = gH[(size_t)(jb + sj0) * 8 + sc];
    int4 ph1 = gH[(size_t)(jb + 32 + sj0) * 8 + sc];
    int4 pl0 = gL[(size_t)(jb + sj0) * 8 + sc];
    int4 pl1 = gL[(size_t)(jb + 32 + sj0) * 8 + sc];
    int2 aC[16], aN[16];
    #pragma unroll
    for (int ks = 0; ks < 4; ks++) {
        aC[ks * 4 + 0] = *(const int2*)(aR0 + ks * 16 + tc * 2);
        aC[ks * 4 + 1] = *(const int2*)(aR1 + ks * 16 + tc * 2);
        aC[ks * 4 + 2] = *(const int2*)(aR0 + ks * 16 + tc * 2 + 8);
        aC[ks * 4 + 3] = *(const int2*)(aR1 + ks * 16 + tc * 2 + 8);
    }

    for (int st = 0; st < 64; st++) {
        __syncthreads();   // previous compute done reading whH/whL (also covers s2S init)
        *(int4*)(whH + sj0 * 144 + sc * 16)        = ph0;
        *(int4*)(whH + (sj0 + 32) * 144 + sc * 16) = ph1;
        *(int4*)(whL + sj0 * 144 + sc * 16)        = pl0;
        *(int4*)(whL + (sj0 + 32) * 144 + sc * 16) = pl1;
        __syncthreads();

        // ---- prefetch subtile st+1 (hidden under ~1000 cyc of compute) ----
        if (st < 63) {
            int jn = jb + (st + 1) * 64;
            ph0 = gH[(size_t)(jn + sj0) * 8 + sc];
            ph1 = gH[(size_t)(jn + 32 + sj0) * 8 + sc];
            pl0 = gL[(size_t)(jn + sj0) * 8 + sc];
            pl1 = gL[(size_t)(jn + 32 + sj0) * 8 + sc];
            const int* bR0 = aR0 + (st + 1) * 64;
            const int* bR1 = aR1 + (st + 1) * 64;
            #pragma unroll
            for (int ks = 0; ks < 4; ks++) {
                aN[ks * 4 + 0] = *(const int2*)(bR0 + ks * 16 + tc * 2);
                aN[ks * 4 + 1] = *(const int2*)(bR1 + ks * 16 + tc * 2);
                aN[ks * 4 + 2] = *(const int2*)(bR0 + ks * 16 + tc * 2 + 8);
                aN[ks * 4 + 3] = *(const int2*)(bR1 + ks * 16 + tc * 2 + 8);
            }
        }

        // ---- 4 k-steps of 16 j ----
        #pragma unroll
        for (int ks = 0; ks < 4; ks++) {
            int j0 = ks * 16;
            float2 sa = *(const float2*)&s2S[st * 64 + j0 + tc * 2];
            float2 sb = *(const float2*)&s2S[st * 64 + j0 + tc * 2 + 8];
            u32 ahi[4], alo[4];
            // A frag order: a0=(g,k0..1) a1=(g+8,k0..1) a2=(g,k8..9) a3=(g+8,k8..9)
            #pragma unroll
            for (int q = 0; q < 4; q++) {
                int2 av = aC[ks * 4 + q];
                float s1v  = (q & 1) ? s1v1 : s1v0;
                float2 s2p = (q >> 1) ? sb : sa;
                float x0 = s1v + s2p.x, x1 = s1v + s2p.y;
                float l0 = fmaxf(x0, 0.2f * x0), l1 = fmaxf(x1, 0.2f * x1);
                float e0 = fmaf(l0, 1.44269504f, -8.0f);   // w = exp(lr)*2^-8
                float e1 = fmaf(l1, 1.44269504f, -8.0f);
                e0 = (av.x > 0) ? e0 : -127.0f;
                e1 = (av.y > 0) ? e1 : -127.0f;
                float w0, w1;
                asm("ex2.approx.ftz.f32 %0, %1;" : "=f"(w0) : "f"(e0));
                asm("ex2.approx.ftz.f32 %0, %1;" : "=f"(w1) : "f"(e1));
                if (q & 1) z1 += w0 + w1; else z0 += w0 + w1;
                u32 hreg;
                asm("cvt.rn.satfinite.f16x2.f32 %0, %1, %2;" : "=r"(hreg) : "f"(w1), "f"(w0));
                float hf0, hf1;
                asm("{.reg .f16 l,h; mov.b32 {l,h}, %2; cvt.f32.f16 %0, l; cvt.f32.f16 %1, h;}"
                    : "=f"(hf0), "=f"(hf1) : "r"(hreg));
                u32 lreg;
                asm("cvt.rn.satfinite.f16x2.f32 %0, %1, %2;" : "=r"(lreg)
                    : "f"(w1 - hf1), "f"(w0 - hf0));
                ahi[q] = hreg; alo[q] = lreg;
            }
            u32 abH = whHb + j0 * 144 + laneoff;
            u32 abL = whLb + j0 * 144 + laneoff;
            #pragma unroll
            for (int nb = 0; nb < 4; nb++) {    // n-tiles 2nb, 2nb+1
                u32 bh0, bh1, bh2, bh3, bl0, bl1, bl2, bl3;
                asm volatile("ldmatrix.sync.aligned.m8n8.x4.trans.shared.b16 {%0,%1,%2,%3}, [%4];"
                    : "=r"(bh0), "=r"(bh1), "=r"(bh2), "=r"(bh3) : "r"(abH + nb * 32));
                asm volatile("ldmatrix.sync.aligned.m8n8.x4.trans.shared.b16 {%0,%1,%2,%3}, [%4];"
                    : "=r"(bl0), "=r"(bl1), "=r"(bl2), "=r"(bl3) : "r"(abL + nb * 32));
                MMA(D[nb * 2],     ahi, bh0, bh1);
                MMA(D[nb * 2],     ahi, bl0, bl1);
                MMA(D[nb * 2],     alo, bh0, bh1);
                MMA(D[nb * 2 + 1], ahi, bh2, bh3);
                MMA(D[nb * 2 + 1], ahi, bl2, bl3);
                MMA(D[nb * 2 + 1], alo, bh2, bh3);
            }
        }
        if (st < 63) {
            #pragma unroll
            for (int q = 0; q < 16; q++) aC[q] = aN[q];
        }
    }

    // ---- epilogue: Z quad-reduce + partial stores ----
    z0 += __shfl_xor_sync(0xffffffffu, z0, 1);
    z0 += __shfl_xor_sync(0xffffffffu, z0, 2);
    z1 += __shfl_xor_sync(0xffffffffu, z1, 1);
    z1 += __shfl_xor_sync(0xffffffffu, z1, 2);
    if (tc == 0) {
        g_Zp[blk * RT + wid * 16 + g]     = z0;
        g_Zp[blk * RT + wid * 16 + 8 + g] = z1;
    }
    float* db = g_Dp + (size_t)blk * RT * FOUT + (size_t)(wid * 16 + g) * FOUT + tc * 2;
    #pragma unroll
    for (int nt = 0; nt < 8; nt++) {
        *(float2*)(db + nt * 8)             = make_float2(D[nt][0], D[nt][1]);
        *(float2*)(db + 8 * FOUT + nt * 8)  = make_float2(D[nt][2], D[nt][3]);
    }
}

// ---------------------------------------------------------------------------
// Kernel 3: combine j-halves: out = elu((D0+D1)/(Z0+Z1))  (2^-8 scale cancels)
// ---------------------------------------------------------------------------
__global__ __launch_bounds__(256) void k_comb(float* __restrict__ out) {
    int idx = blockIdx.x * 256 + threadIdx.x;   // x4 floats
    int i  = idx >> 4;
    int f4 = (idx & 15) * 4;
    int rt = i >> 7, r = i & 127;
    const float4 d0 = *(const float4*)(g_Dp + (size_t)(rt * 2)     * (RT * FOUT) + r * FOUT + f4);
    const float4 d1 = *(const float4*)(g_Dp + (size_t)(rt * 2 + 1) * (RT * FOUT) + r * FOUT + f4);
    float z = g_Zp[(rt * 2) * RT + r] + g_Zp[(rt * 2 + 1) * RT + r];
    float inv = 1.0f / z;
    float v[4] = {(d0.x + d1.x) * inv, (d0.y + d1.y) * inv,
                  (d0.z + d1.z) * inv, (d0.w + d1.w) * inv};
    #pragma unroll
    for (int c = 0; c < 4; c++) v[c] = (v[c] > 0.f) ? v[c] : expm1f(v[c]);
    *(float4*)(out + (size_t)i * FOUT + f4) = make_float4(v[0], v[1], v[2], v[3]);
}

// ---------------------------------------------------------------------------
extern "C" void kernel_launch(void* const* d_in, const int* in_sizes, int n_in,
                              void* d_out, int out_size) {
    const float* h   = (const float*)d_in[0];
    const int*   adj = (const int*)  d_in[1];
    const float* W   = (const float*)d_in[2];
    const float* a   = (const float*)d_in[3];
    float* out = (float*)d_out;

    k_prep<<<NN / 16, 256>>>(h, W, a);
    k_main<<<NBLK, 256>>>(adj);
    k_comb<<<NN * FOUT / 4 / 256, 256>>>(out);
}

// round 10
// speedup vs baseline: 15.6040x; 1.0500x over previous
#include <cuda_runtime.h>
#include <cuda_fp16.h>
#include <cstdint>

#define NN    8192
#define FIN   256
#define FOUT  64
#define RT    128
#define NBLK  128

typedef unsigned int u32;

// ---- global scratch (no cudaMalloc allowed) ----
__device__ float g_s1[NN];
__device__ __align__(16) float g_s2[NN];
__device__ __align__(16) __half g_Wh_hi[NN * FOUT];   // [j][f] row-major
__device__ __align__(16) __half g_Wh_lo[NN * FOUT];
__device__ __align__(16) float g_Dp[NBLK * RT * FOUT];
__device__ float g_Zp[NBLK * RT];

static __device__ __forceinline__ u32 smem_u32(const void* p) {
    u32 a;
    asm("{ .reg .u64 t; cvta.to.shared.u64 t, %1; cvt.u32.u64 %0, t; }" : "=r"(a) : "l"(p));
    return a;
}

#define MMA(d, a, b0_, b1_)                                                     \
    asm volatile("mma.sync.aligned.m16n8k16.row.col.f32.f16.f16.f32 "           \
        "{%0,%1,%2,%3}, {%4,%5,%6,%7}, {%8,%9}, {%0,%1,%2,%3};"                 \
        : "+f"(d[0]), "+f"(d[1]), "+f"(d[2]), "+f"(d[3])                        \
        : "r"(a[0]), "r"(a[1]), "r"(a[2]), "r"(a[3]), "r"(b0_), "r"(b1_))

// ---------------------------------------------------------------------------
// Kernel 1: Wh = h@W ; s1 = Wh@a1 ; s2 = Wh@a2 ; fp16 hi/lo split of Wh
// v2: W transposed in smem (stride 260: 16B-aligned rows, conflict-free
// LDS.128), float4 h tile, 16 FFMA per 5 LDS.128.
// dyn smem: Wt 64x260 floats (66560B) + hS 16x256 floats (16384B) = 82944B
// ---------------------------------------------------------------------------
__global__ __launch_bounds__(256) void k_prep(const float* __restrict__ h,
                                              const float* __restrict__ W,
                                              const float* __restrict__ a) {
    extern __shared__ float dsm[];
    float* Wt = dsm;                    // [64][260]
    float* hS = dsm + 64 * 260;         // [16][256]
    __shared__ float redS[2][8][4];
    int t  = threadIdx.x;
    int k  = t & 63;
    int rg = t >> 6;
    int rowBase = blockIdx.x * 16;

    // stage h tile (16 x 256 f32) as float4
    const float4* hb4 = (const float4*)(h + (size_t)rowBase * FIN);
    float4* hS4 = (float4*)hS;
    #pragma unroll
    for (int p = 0; p < 4; p++) hS4[p * 256 + t] = hb4[p * 256 + t];

    // stage W transposed: Wt[k][c] = W[c][k]
    const float4* W4 = (const float4*)W;     // idx = c*16 + k4
    #pragma unroll
    for (int it = 0; it < 16; it++) {
        int idx4 = t + it * 256;             // 0..4095
        int c  = idx4 >> 4;
        int k4 = (idx4 & 15) << 2;
        float4 wv = W4[idx4];
        Wt[(k4 + 0) * 260 + c] = wv.x;
        Wt[(k4 + 1) * 260 + c] = wv.y;
        Wt[(k4 + 2) * 260 + c] = wv.z;
        Wt[(k4 + 3) * 260 + c] = wv.w;
    }
    __syncthreads();

    float acc[4] = {0.f, 0.f, 0.f, 0.f};
    const float4* wrow = (const float4*)(Wt + k * 260);
    #pragma unroll 2
    for (int c4 = 0; c4 < 64; c4++) {
        float4 wv = wrow[c4];
        #pragma unroll
        for (int rr = 0; rr < 4; rr++) {
            float4 hv = ((const float4*)(hS + (rg * 4 + rr) * 256))[c4];
            acc[rr] = fmaf(hv.x, wv.x, acc[rr]);
            acc[rr] = fmaf(hv.y, wv.y, acc[rr]);
            acc[rr] = fmaf(hv.z, wv.z, acc[rr]);
            acc[rr] = fmaf(hv.w, wv.w, acc[rr]);
        }
    }

    float a1v = a[k];
    float a2v = a[FOUT + k];
    int wid = t >> 5;
    #pragma unroll
    for (int rr = 0; rr < 4; rr++) {
        int j = rowBase + rg * 4 + rr;
        __half hv = __float2half(acc[rr]);
        float hf  = __half2float(hv);
        __half lv = __float2half(acc[rr] - hf);
        g_Wh_hi[j * FOUT + k] = hv;
        g_Wh_lo[j * FOUT + k] = lv;

        float p1 = acc[rr] * a1v;
        float p2 = acc[rr] * a2v;
        #pragma unroll
        for (int o = 16; o > 0; o >>= 1) {
            p1 += __shfl_down_sync(0xffffffffu, p1, o);
            p2 += __shfl_down_sync(0xffffffffu, p2, o);
        }
        if ((t & 31) == 0) { redS[0][wid][rr] = p1; redS[1][wid][rr] = p2; }
    }
    __syncthreads();
    if (k < 4) {
        int rr  = k;
        int row = rowBase + rg * 4 + rr;
        g_s1[row] = redS[0][2 * rg][rr] + redS[0][2 * rg + 1][rr];
        g_s2[row] = redS[1][2 * rg][rr] + redS[1][2 * rg + 1][rr];
    }
}

// ---------------------------------------------------------------------------
// Kernel 2: mma.sync flash-GAT, 2-pass fp16 split (A_hi x B_hi + A_hi x B_lo;
// A_lo pass dropped: adds ~1e-4 random-sign rel err, -33% MMA, -57% XU).
// Double-buffered Wh tiles -> ONE __syncthreads per subtile.
// dyn smem: s2S 16KB @0, whH[2] @16384 (2x9216), whL[2] @34816 = 53248B
// ---------------------------------------------------------------------------
__global__ __launch_bounds__(256) void k_main(const int* __restrict__ adj) {
    extern __shared__ char smx[];
    float* s2S = (float*)smx;
    char*  whH = smx + 16384;    // [2][64*144]
    char*  whL = smx + 34816;

    int t = threadIdx.x, lane = t & 31, wid = t >> 5;
    int blk = blockIdx.x;
    int i0 = (blk >> 1) * RT;
    int jb = (blk & 1) * 4096;
    int g = lane >> 2, tc = lane & 3;

    #pragma unroll
    for (int q = 0; q < 16; q++) s2S[t + q * 256] = g_s2[jb + t + q * 256];

    int row0 = i0 + wid * 16 + g;
    float s1v0 = g_s1[row0], s1v1 = g_s1[row0 + 8];
    const int* aR0 = adj + (size_t)row0 * NN + jb;
    const int* aR1 = aR0 + (size_t)8 * NN;

    float D[8][4];
    #pragma unroll
    for (int n = 0; n < 8; n++) { D[n][0] = D[n][1] = D[n][2] = D[n][3] = 0.f; }
    float z0 = 0.f, z1 = 0.f;

    u32 whHb = smem_u32(whH), whLb = smem_u32(whL);
    // ldmatrix.x4 lane address: matrix m = lane>>3 -> (khalf = m&1, n-sub = m>>1)
    int laneoff = (((lane >> 3) & 1) * 8 + (lane & 7)) * 144 + (lane >> 4) * 16;

    int sj0 = t >> 3, sc = t & 7;   // staging: chunk fid=t -> row sj0, 16B chunk sc
    const int4* gH = (const int4*)g_Wh_hi;  // int4 idx = j*8 + c
    const int4* gL = (const int4*)g_Wh_lo;

    // ---- prefetch subtile 0: Wh + adj ----
    int4 ph0 = gH[(size_t)(jb + sj0) * 8 + sc];
    int4 ph1 = gH[(size_t)(jb + 32 + sj0) * 8 + sc];
    int4 pl0 = gL[(size_t)(jb + sj0) * 8 + sc];
    int4 pl1 = gL[(size_t)(jb + 32 + sj0) * 8 + sc];
    int2 aC[16], aN[16];
    #pragma unroll
    for (int ks = 0; ks < 4; ks++) {
        aC[ks * 4 + 0] = *(const int2*)(aR0 + ks * 16 + tc * 2);
        aC[ks * 4 + 1] = *(const int2*)(aR1 + ks * 16 + tc * 2);
        aC[ks * 4 + 2] = *(const int2*)(aR0 + ks * 16 + tc * 2 + 8);
        aC[ks * 4 + 3] = *(const int2*)(aR1 + ks * 16 + tc * 2 + 8);
    }

    for (int st = 0; st < 64; st++) {
        int bo = (st & 1) * 9216;
        // stage current subtile into buffer st&1 (prev readers of this buffer
        // were compute(st-2), which all warps finished before passing
        // sync(st-1) -> WAR-safe with a single sync per subtile)
        *(int4*)(whH + bo + sj0 * 144 + sc * 16)        = ph0;
        *(int4*)(whH + bo + (sj0 + 32) * 144 + sc * 16) = ph1;
        *(int4*)(whL + bo + sj0 * 144 + sc * 16)        = pl0;
        *(int4*)(whL + bo + (sj0 + 32) * 144 + sc * 16) = pl1;
        __syncthreads();

        // ---- prefetch subtile st+1 (hidden under compute) ----
        if (st < 63) {
            int jn = jb + (st + 1) * 64;
            ph0 = gH[(size_t)(jn + sj0) * 8 + sc];
            ph1 = gH[(size_t)(jn + 32 + sj0) * 8 + sc];
            pl0 = gL[(size_t)(jn + sj0) * 8 + sc];
            pl1 = gL[(size_t)(jn + 32 + sj0) * 8 + sc];
            const int* bR0 = aR0 + (st + 1) * 64;
            const int* bR1 = aR1 + (st + 1) * 64;
            #pragma unroll
            for (int ks = 0; ks < 4; ks++) {
                aN[ks * 4 + 0] = *(const int2*)(bR0 + ks * 16 + tc * 2);
                aN[ks * 4 + 1] = *(const int2*)(bR1 + ks * 16 + tc * 2);
                aN[ks * 4 + 2] = *(const int2*)(bR0 + ks * 16 + tc * 2 + 8);
                aN[ks * 4 + 3] = *(const int2*)(bR1 + ks * 16 + tc * 2 + 8);
            }
        }

        // ---- 4 k-steps of 16 j ----
        #pragma unroll
        for (int ks = 0; ks < 4; ks++) {
            int j0 = ks * 16;
            float2 sa = *(const float2*)&s2S[st * 64 + j0 + tc * 2];
            float2 sb = *(const float2*)&s2S[st * 64 + j0 + tc * 2 + 8];
            u32 ahi[4];
            // A frag order: a0=(g,k0..1) a1=(g+8,k0..1) a2=(g,k8..9) a3=(g+8,k8..9)
            #pragma unroll
            for (int q = 0; q < 4; q++) {
                int2 av = aC[ks * 4 + q];
                float s1v  = (q & 1) ? s1v1 : s1v0;
                float2 s2p = (q >> 1) ? sb : sa;
                float x0 = s1v + s2p.x, x1 = s1v + s2p.y;
                float l0 = fmaxf(x0, 0.2f * x0), l1 = fmaxf(x1, 0.2f * x1);
                float e0 = fmaf(l0, 1.44269504f, -8.0f);   // w = exp(lr)*2^-8
                float e1 = fmaf(l1, 1.44269504f, -8.0f);
                e0 = (av.x > 0) ? e0 : -127.0f;
                e1 = (av.y > 0) ? e1 : -127.0f;
                float w0, w1;
                asm("ex2.approx.ftz.f32 %0, %1;" : "=f"(w0) : "f"(e0));
                asm("ex2.approx.ftz.f32 %0, %1;" : "=f"(w1) : "f"(e1));
                if (q & 1) z1 += w0 + w1; else z0 += w0 + w1;
                asm("cvt.rn.satfinite.f16x2.f32 %0, %1, %2;" : "=r"(ahi[q]) : "f"(w1), "f"(w0));
            }
            u32 abH = whHb + bo + j0 * 144 + laneoff;
            u32 abL = whLb + bo + j0 * 144 + laneoff;
            #pragma unroll
            for (int nb = 0; nb < 4; nb++) {    // n-tiles 2nb, 2nb+1
                u32 bh0, bh1, bh2, bh3, bl0, bl1, bl2, bl3;
                asm volatile("ldmatrix.sync.aligned.m8n8.x4.trans.shared.b16 {%0,%1,%2,%3}, [%4];"
                    : "=r"(bh0), "=r"(bh1), "=r"(bh2), "=r"(bh3) : "r"(abH + nb * 32));
                asm volatile("ldmatrix.sync.aligned.m8n8.x4.trans.shared.b16 {%0,%1,%2,%3}, [%4];"
                    : "=r"(bl0), "=r"(bl1), "=r"(bl2), "=r"(bl3) : "r"(abL + nb * 32));
                MMA(D[nb * 2],     ahi, bh0, bh1);
                MMA(D[nb * 2],     ahi, bl0, bl1);
                MMA(D[nb * 2 + 1], ahi, bh2, bh3);
                MMA(D[nb * 2 + 1], ahi, bl2, bl3);
            }
        }
        if (st < 63) {
            #pragma unroll
            for (int q = 0; q < 16; q++) aC[q] = aN[q];
        }
    }

    // ---- epilogue: Z quad-reduce + partial stores ----
    z0 += __shfl_xor_sync(0xffffffffu, z0, 1);
    z0 += __shfl_xor_sync(0xffffffffu, z0, 2);
    z1 += __shfl_xor_sync(0xffffffffu, z1, 1);
    z1 += __shfl_xor_sync(0xffffffffu, z1, 2);
    if (tc == 0) {
        g_Zp[blk * RT + wid * 16 + g]     = z0;
        g_Zp[blk * RT + wid * 16 + 8 + g] = z1;
    }
    float* db = g_Dp + (size_t)blk * RT * FOUT + (size_t)(wid * 16 + g) * FOUT + tc * 2;
    #pragma unroll
    for (int nt = 0; nt < 8; nt++) {
        *(float2*)(db + nt * 8)             = make_float2(D[nt][0], D[nt][1]);
        *(float2*)(db + 8 * FOUT + nt * 8)  = make_float2(D[nt][2], D[nt][3]);
    }
}

// ---------------------------------------------------------------------------
// Kernel 3: combine j-halves: out = elu((D0+D1)/(Z0+Z1))  (2^-8 scale cancels)
// ---------------------------------------------------------------------------
__global__ __launch_bounds__(256) void k_comb(float* __restrict__ out) {
    int idx = blockIdx.x * 256 + threadIdx.x;   // x4 floats
    int i  = idx >> 4;
    int f4 = (idx & 15) * 4;
    int rt = i >> 7, r = i & 127;
    const float4 d0 = *(const float4*)(g_Dp + (size_t)(rt * 2)     * (RT * FOUT) + r * FOUT + f4);
    const float4 d1 = *(const float4*)(g_Dp + (size_t)(rt * 2 + 1) * (RT * FOUT) + r * FOUT + f4);
    float z = g_Zp[(rt * 2) * RT + r] + g_Zp[(rt * 2 + 1) * RT + r];
    float inv = 1.0f / z;
    float v[4] = {(d0.x + d1.x) * inv, (d0.y + d1.y) * inv,
                  (d0.z + d1.z) * inv, (d0.w + d1.w) * inv};
    #pragma unroll
    for (int c = 0; c < 4; c++) v[c] = (v[c] > 0.f) ? v[c] : expm1f(v[c]);
    *(float4*)(out + (size_t)i * FOUT + f4) = make_float4(v[0], v[1], v[2], v[3]);
}

// ---------------------------------------------------------------------------
extern "C" void kernel_launch(void* const* d_in, const int* in_sizes, int n_in,
                              void* d_out, int out_size) {
    const float* h   = (const float*)d_in[0];
    const int*   adj = (const int*)  d_in[1];
    const float* W   = (const float*)d_in[2];
    const float* a   = (const float*)d_in[3];
    float* out = (float*)d_out;

    cudaFuncSetAttribute(k_prep, cudaFuncAttributeMaxDynamicSharedMemorySize, 82944);
    cudaFuncSetAttribute(k_main, cudaFuncAttributeMaxDynamicSharedMemorySize, 53248);
    k_prep<<<NN / 16, 256, 82944>>>(h, W, a);
    k_main<<<NBLK, 256, 53248>>>(adj);
    k_comb<<<NN * FOUT / 4 / 256, 256>>>(out);
}

// round 11
// speedup vs baseline: 19.1715x; 1.2286x over previous
#include <cuda_runtime.h>
#include <cuda_fp16.h>
#include <cstdint>

#define NN    8192
#define FIN   256
#define FOUT  64
#define RT    128
#define NBLK  256      // 64 row-tiles x 4 j-quarters
#define JT    2048     // j per block
#define NSUB  32       // subtiles of 64 j

typedef unsigned int u32;

// ---- global scratch (no cudaMalloc allowed) ----
__device__ float g_s1[NN];
__device__ __align__(16) float g_s2[NN];
__device__ __align__(16) __half g_Wh_hi[NN * FOUT];   // [j][f] row-major
__device__ __align__(16) __half g_Wh_lo[NN * FOUT];
__device__ __align__(16) float g_Dp[NBLK * RT * FOUT];
__device__ float g_Zp[NBLK * RT];

static __device__ __forceinline__ u32 smem_u32(const void* p) {
    u32 a;
    asm("{ .reg .u64 t; cvta.to.shared.u64 t, %1; cvt.u32.u64 %0, t; }" : "=r"(a) : "l"(p));
    return a;
}

#define MMA(d, a, b0_, b1_)                                                     \
    asm volatile("mma.sync.aligned.m16n8k16.row.col.f32.f16.f16.f32 "           \
        "{%0,%1,%2,%3}, {%4,%5,%6,%7}, {%8,%9}, {%0,%1,%2,%3};"                 \
        : "+f"(d[0]), "+f"(d[1]), "+f"(d[2]), "+f"(d[3])                        \
        : "r"(a[0]), "r"(a[1]), "r"(a[2]), "r"(a[3]), "r"(b0_), "r"(b1_))

// ---------------------------------------------------------------------------
// Kernel 1 (v3): Wh = h@W ; s1/s2 ; fp16 hi/lo split.
// 256 blocks x 32 rows. Conflict-free W transpose: thread (k'=t&63, rg=t>>6)
// loads W[(4u+i)*64+k'] (coalesced scalar LDG) and stores one STS.128 to
// Wt[k'][4u] (banks 4k' mod 32, distinct per 8-lane phase).
// dyn smem: Wt 64x260 f32 (66560B) + hS 32x256 f32 (32768B) = 99328B
// ---------------------------------------------------------------------------
__global__ __launch_bounds__(256, 2) void k_prep(const float* __restrict__ h,
                                                 const float* __restrict__ W,
                                                 const float* __restrict__ a) {
    extern __shared__ float dsm[];
    float* Wt = dsm;                    // [64][260]
    float* hS = dsm + 64 * 260;         // [32][256]
    __shared__ float redS[2][8][8];
    int t  = threadIdx.x;
    int k  = t & 63;
    int rg = t >> 6;
    int rowBase = blockIdx.x * 32;

    // stage h tile (32 x 256 f32) as float4
    const float4* hb4 = (const float4*)(h + (size_t)rowBase * FIN);
    float4* hS4 = (float4*)hS;
    #pragma unroll
    for (int p = 0; p < 8; p++) hS4[p * 256 + t] = hb4[p * 256 + t];

    // stage W transposed, conflict-free
    #pragma unroll
    for (int u16 = 0; u16 < 16; u16++) {
        int u = rg * 16 + u16;          // c4 index 0..63
        float4 v;
        v.x = __ldg(&W[(4 * u + 0) * FOUT + k]);
        v.y = __ldg(&W[(4 * u + 1) * FOUT + k]);
        v.z = __ldg(&W[(4 * u + 2) * FOUT + k]);
        v.w = __ldg(&W[(4 * u + 3) * FOUT + k]);
        *(float4*)(Wt + k * 260 + 4 * u) = v;
    }
    __syncthreads();

    float acc[8];
    #pragma unroll
    for (int rr = 0; rr < 8; rr++) acc[rr] = 0.f;
    const float4* wrow = (const float4*)(Wt + k * 260);
    #pragma unroll 2
    for (int c4 = 0; c4 < 64; c4++) {
        float4 wv = wrow[c4];
        #pragma unroll
        for (int rr = 0; rr < 8; rr++) {
            float4 hv = ((const float4*)(hS + (rg * 8 + rr) * 256))[c4];
            acc[rr] = fmaf(hv.x, wv.x, acc[rr]);
            acc[rr] = fmaf(hv.y, wv.y, acc[rr]);
            acc[rr] = fmaf(hv.z, wv.z, acc[rr]);
            acc[rr] = fmaf(hv.w, wv.w, acc[rr]);
        }
    }

    float a1v = a[k];
    float a2v = a[FOUT + k];
    int wid = t >> 5;
    #pragma unroll
    for (int rr = 0; rr < 8; rr++) {
        int j = rowBase + rg * 8 + rr;
        __half hv = __float2half(acc[rr]);
        float hf  = __half2float(hv);
        __half lv = __float2half(acc[rr] - hf);
        g_Wh_hi[j * FOUT + k] = hv;
        g_Wh_lo[j * FOUT + k] = lv;

        float p1 = acc[rr] * a1v;
        float p2 = acc[rr] * a2v;
        #pragma unroll
        for (int o = 16; o > 0; o >>= 1) {
            p1 += __shfl_down_sync(0xffffffffu, p1, o);
            p2 += __shfl_down_sync(0xffffffffu, p2, o);
        }
        if ((t & 31) == 0) { redS[0][wid][rr] = p1; redS[1][wid][rr] = p2; }
    }
    __syncthreads();
    if (k < 8) {
        int rr  = k;
        int row = rowBase + rg * 8 + rr;
        g_s1[row] = redS[0][2 * rg][rr] + redS[0][2 * rg + 1][rr];
        g_s2[row] = redS[1][2 * rg][rr] + redS[1][2 * rg + 1][rr];
    }
}

// ---------------------------------------------------------------------------
// Kernel 2 (v3): mma.sync flash-GAT, 2-pass fp16 split, adj as BITMASK
// (1 u32/thread/subtile instead of 16 int2 regs -> ~75 regs, 2 blocks/SM).
// Block (rt, jq): 128 rows x 2048 j, 32 subtiles of 64. One sync/subtile.
// static smem: s2S 8KB + whH 2x9216 + whL 2x9216 = 44.8KB
// ---------------------------------------------------------------------------
__global__ __launch_bounds__(256, 2) void k_main(const int* __restrict__ adj) {
    __shared__ float s2S[JT];
    __shared__ __align__(16) char whH[2 * 9216];
    __shared__ __align__(16) char whL[2 * 9216];

    int t = threadIdx.x, lane = t & 31, wid = t >> 5;
    int blk = blockIdx.x;
    int i0 = (blk >> 2) * RT;
    int jb = (blk & 3) * JT;
    int g = lane >> 2, tc = lane & 3;

    #pragma unroll
    for (int q = 0; q < JT / 256; q++) s2S[t + q * 256] = g_s2[jb + t + q * 256];

    int row0 = i0 + wid * 16 + g;
    float s1v0 = g_s1[row0], s1v1 = g_s1[row0 + 8];
    const int* aR0 = adj + (size_t)row0 * NN + jb;
    const int* aR1 = aR0 + (size_t)8 * NN;

    float D[8][4];
    #pragma unroll
    for (int n = 0; n < 8; n++) { D[n][0] = D[n][1] = D[n][2] = D[n][3] = 0.f; }
    float z0 = 0.f, z1 = 0.f;

    u32 whHb = smem_u32(whH), whLb = smem_u32(whL);
    int laneoff = (((lane >> 3) & 1) * 8 + (lane & 7)) * 144 + (lane >> 4) * 16;

    int sj0 = t >> 3, sc = t & 7;
    const int4* gH = (const int4*)g_Wh_hi;
    const int4* gL = (const int4*)g_Wh_lo;

    // adj bitmask loader for subtile s: bit(ks*8+q*2+{0,1})
    auto loadBits = [&](int s) -> u32 {
        const int* b0 = aR0 + s * 64;
        const int* b1 = aR1 + s * 64;
        u32 m = 0;
        #pragma unroll
        for (int ks = 0; ks < 4; ks++) {
            int2 v0 = *(const int2*)(b0 + ks * 16 + tc * 2);
            int2 v1 = *(const int2*)(b1 + ks * 16 + tc * 2);
            int2 v2 = *(const int2*)(b0 + ks * 16 + tc * 2 + 8);
            int2 v3 = *(const int2*)(b1 + ks * 16 + tc * 2 + 8);
            u32 base = ks * 8;
            m |= (v0.x > 0 ? 1u : 0u) << (base + 0);
            m |= (v0.y > 0 ? 1u : 0u) << (base + 1);
            m |= (v1.x > 0 ? 1u : 0u) << (base + 2);
            m |= (v1.y > 0 ? 1u : 0u) << (base + 3);
            m |= (v2.x > 0 ? 1u : 0u) << (base + 4);
            m |= (v2.y > 0 ? 1u : 0u) << (base + 5);
            m |= (v3.x > 0 ? 1u : 0u) << (base + 6);
            m |= (v3.y > 0 ? 1u : 0u) << (base + 7);
        }
        return m;
    };

    // ---- prefetch subtile 0 ----
    int4 ph0 = gH[(size_t)(jb + sj0) * 8 + sc];
    int4 ph1 = gH[(size_t)(jb + 32 + sj0) * 8 + sc];
    int4 pl0 = gL[(size_t)(jb + sj0) * 8 + sc];
    int4 pl1 = gL[(size_t)(jb + 32 + sj0) * 8 + sc];
    u32 bC = loadBits(0), bN = 0;

    for (int st = 0; st < NSUB; st++) {
        int bo = (st & 1) * 9216;
        *(int4*)(whH + bo + sj0 * 144 + sc * 16)        = ph0;
        *(int4*)(whH + bo + (sj0 + 32) * 144 + sc * 16) = ph1;
        *(int4*)(whL + bo + sj0 * 144 + sc * 16)        = pl0;
        *(int4*)(whL + bo + (sj0 + 32) * 144 + sc * 16) = pl1;
        __syncthreads();

        // ---- prefetch subtile st+1 ----
        if (st < NSUB - 1) {
            int jn = jb + (st + 1) * 64;
            ph0 = gH[(size_t)(jn + sj0) * 8 + sc];
            ph1 = gH[(size_t)(jn + 32 + sj0) * 8 + sc];
            pl0 = gL[(size_t)(jn + sj0) * 8 + sc];
            pl1 = gL[(size_t)(jn + 32 + sj0) * 8 + sc];
            bN = loadBits(st + 1);
        }

        // ---- 4 k-steps of 16 j ----
        #pragma unroll
        for (int ks = 0; ks < 4; ks++) {
            int j0 = ks * 16;
            float2 sa = *(const float2*)&s2S[st * 64 + j0 + tc * 2];
            float2 sb = *(const float2*)&s2S[st * 64 + j0 + tc * 2 + 8];
            u32 ahi[4];
            #pragma unroll
            for (int q = 0; q < 4; q++) {
                u32 bb = bC >> (ks * 8 + q * 2);
                float s1v  = (q & 1) ? s1v1 : s1v0;
                float2 s2p = (q >> 1) ? sb : sa;
                float x0 = s1v + s2p.x, x1 = s1v + s2p.y;
                float l0 = fmaxf(x0, 0.2f * x0), l1 = fmaxf(x1, 0.2f * x1);
                float e0 = fmaf(l0, 1.44269504f, -8.0f);   // w = exp(lr)*2^-8
                float e1 = fmaf(l1, 1.44269504f, -8.0f);
                e0 = (bb & 1u) ? e0 : -127.0f;
                e1 = (bb & 2u) ? e1 : -127.0f;
                float w0, w1;
                asm("ex2.approx.ftz.f32 %0, %1;" : "=f"(w0) : "f"(e0));
                asm("ex2.approx.ftz.f32 %0, %1;" : "=f"(w1) : "f"(e1));
                if (q & 1) z1 += w0 + w1; else z0 += w0 + w1;
                asm("cvt.rn.satfinite.f16x2.f32 %0, %1, %2;" : "=r"(ahi[q]) : "f"(w1), "f"(w0));
            }
            u32 abH = whHb + bo + j0 * 144 + laneoff;
            u32 abL = whLb + bo + j0 * 144 + laneoff;
            #pragma unroll
            for (int nb = 0; nb < 4; nb++) {
                u32 bh0, bh1, bh2, bh3, bl0, bl1, bl2, bl3;
                asm volatile("ldmatrix.sync.aligned.m8n8.x4.trans.shared.b16 {%0,%1,%2,%3}, [%4];"
                    : "=r"(bh0), "=r"(bh1), "=r"(bh2), "=r"(bh3) : "r"(abH + nb * 32));
                asm volatile("ldmatrix.sync.aligned.m8n8.x4.trans.shared.b16 {%0,%1,%2,%3}, [%4];"
                    : "=r"(bl0), "=r"(bl1), "=r"(bl2), "=r"(bl3) : "r"(abL + nb * 32));
                MMA(D[nb * 2],     ahi, bh0, bh1);
                MMA(D[nb * 2],     ahi, bl0, bl1);
                MMA(D[nb * 2 + 1], ahi, bh2, bh3);
                MMA(D[nb * 2 + 1], ahi, bl2, bl3);
            }
        }
        bC = bN;
    }

    // ---- epilogue: Z quad-reduce + partial stores ----
    z0 += __shfl_xor_sync(0xffffffffu, z0, 1);
    z0 += __shfl_xor_sync(0xffffffffu, z0, 2);
    z1 += __shfl_xor_sync(0xffffffffu, z1, 1);
    z1 += __shfl_xor_sync(0xffffffffu, z1, 2);
    if (tc == 0) {
        g_Zp[blk * RT + wid * 16 + g]     = z0;
        g_Zp[blk * RT + wid * 16 + 8 + g] = z1;
    }
    float* db = g_Dp + (size_t)blk * RT * FOUT + (size_t)(wid * 16 + g) * FOUT + tc * 2;
    #pragma unroll
    for (int nt = 0; nt < 8; nt++) {
        *(float2*)(db + nt * 8)             = make_float2(D[nt][0], D[nt][1]);
        *(float2*)(db + 8 * FOUT + nt * 8)  = make_float2(D[nt][2], D[nt][3]);
    }
}

// ---------------------------------------------------------------------------
// Kernel 3: combine 4 j-quarters: out = elu(SumD/SumZ)
// ---------------------------------------------------------------------------
__global__ __launch_bounds__(256) void k_comb(float* __restrict__ out) {
    int idx = blockIdx.x * 256 + threadIdx.x;   // x4 floats
    int i  = idx >> 4;
    int f4 = (idx & 15) * 4;
    int rt = i >> 7, r = i & 127;
    float4 d = make_float4(0.f, 0.f, 0.f, 0.f);
    float z = 0.f;
    #pragma unroll
    for (int p = 0; p < 4; p++) {
        int b = rt * 4 + p;
        const float4 dp = *(const float4*)(g_Dp + (size_t)b * (RT * FOUT) + r * FOUT + f4);
        d.x += dp.x; d.y += dp.y; d.z += dp.z; d.w += dp.w;
        z += g_Zp[b * RT + r];
    }
    float inv = 1.0f / z;
    float v[4] = {d.x * inv, d.y * inv, d.z * inv, d.w * inv};
    #pragma unroll
    for (int c = 0; c < 4; c++) v[c] = (v[c] > 0.f) ? v[c] : expm1f(v[c]);
    *(float4*)(out + (size_t)i * FOUT + f4) = make_float4(v[0], v[1], v[2], v[3]);
}

// ---------------------------------------------------------------------------
extern "C" void kernel_launch(void* const* d_in, const int* in_sizes, int n_in,
                              void* d_out, int out_size) {
    const float* h   = (const float*)d_in[0];
    const int*   adj = (const int*)  d_in[1];
    const float* W   = (const float*)d_in[2];
    const float* a   = (const float*)d_in[3];
    float* out = (float*)d_out;

    cudaFuncSetAttribute(k_prep, cudaFuncAttributeMaxDynamicSharedMemorySize, 99328);
    k_prep<<<NN / 32, 256, 99328>>>(h, W, a);
    k_main<<<NBLK, 256>>>(adj);
    k_comb<<<NN * FOUT / 4 / 256, 256>>>(out);
}

// round 12
// speedup vs baseline: 20.9334x; 1.0919x over previous
#include <cuda_runtime.h>
#include <cuda_fp16.h>
#include <cstdint>

#define NN    8192
#define FIN   256
#define FOUT  64
#define RT    128
#define NBLK  256      // 64 row-tiles x 4 j-quarters
#define JT    2048     // j per block
#define NSUB  32       // subtiles of 64 j

typedef unsigned int u32;

// ---- global scratch (no cudaMalloc allowed) ----
__device__ float g_s1[NN];
__device__ __align__(16) float g_s2[NN];
__device__ __align__(16) __half g_Wh_hi[NN * FOUT];   // [j][f] row-major
__device__ __align__(16) __half g_Wh_lo[NN * FOUT];
__device__ __align__(16) float g_Dp[NBLK * RT * FOUT];
__device__ float g_Zp[NBLK * RT];

static __device__ __forceinline__ u32 smem_u32(const void* p) {
    u32 a;
    asm("{ .reg .u64 t; cvta.to.shared.u64 t, %1; cvt.u32.u64 %0, t; }" : "=r"(a) : "l"(p));
    return a;
}

#define MMA(d, a, b0_, b1_)                                                     \
    asm volatile("mma.sync.aligned.m16n8k16.row.col.f32.f16.f16.f32 "           \
        "{%0,%1,%2,%3}, {%4,%5,%6,%7}, {%8,%9}, {%0,%1,%2,%3};"                 \
        : "+f"(d[0]), "+f"(d[1]), "+f"(d[2]), "+f"(d[3])                        \
        : "r"(a[0]), "r"(a[1]), "r"(a[2]), "r"(a[3]), "r"(b0_), "r"(b1_))

#define MMAT(d, a0_, a1_, a2_, a3_, b0_, b1_)                                   \
    asm volatile("mma.sync.aligned.m16n8k8.row.col.f32.tf32.tf32.f32 "          \
        "{%0,%1,%2,%3}, {%4,%5,%6,%7}, {%8,%9}, {%0,%1,%2,%3};"                 \
        : "+f"(d[0]), "+f"(d[1]), "+f"(d[2]), "+f"(d[3])                        \
        : "r"(a0_), "r"(a1_), "r"(a2_), "r"(a3_), "r"(b0_), "r"(b1_))

static __device__ __forceinline__ u32 tf32cvt(float f) {
    u32 r;
    asm("cvt.rna.tf32.f32 %0, %1;" : "=r"(r) : "f"(f));
    return r;
}

#define CPA(dst, src) asm volatile("cp.async.cg.shared.global [%0], [%1], 16;" :: "r"(dst), "l"(src) : "memory")
#define CPC() asm volatile("cp.async.commit_group;" ::: "memory")
#define CPW0() asm volatile("cp.async.wait_group 0;" ::: "memory")

// ---------------------------------------------------------------------------
// Kernel 1 (v4): Wh = h@W via 3xTF32 tensor-core GEMM; s1/s2; fp16 hi/lo split.
// 128 blocks x 64 rows. 8 warps = 4 m-tiles x 2 n-halves. K=256 in 32 k8-steps.
// smem: hS [64][260] f32 + Wt [n=64][260] f32 = 133120 B (1 block/SM).
// Conflict-free: addr%32 = (4*row + k)%32, lanes (g,tc) -> 4g+tc distinct.
// ---------------------------------------------------------------------------
__global__ __launch_bounds__(256) void k_prep(const float* __restrict__ h,
                                              const float* __restrict__ W,
                                              const float* __restrict__ a) {
    extern __shared__ float dsm[];
    float* hS = dsm;                    // [64][260]
    float* Wt = dsm + 64 * 260;         // [64][260]  ([n][k])
    __shared__ float redS[2][2][64];
    int t = threadIdx.x, lane = t & 31, wid = t >> 5;
    int rowBase = blockIdx.x * 64;

    // stage h tile (64 x 256 f32)
    const float4* hb4 = (const float4*)(h + (size_t)rowBase * FIN);
    #pragma unroll
    for (int p = 0; p < 16; p++) {
        int idx4 = t + p * 256;
        int r = idx4 >> 6, c4 = idx4 & 63;
        float4 v = hb4[idx4];
        *(float4*)(hS + r * 260 + c4 * 4) = v;
    }
    // stage W transposed [n][k], conflict-free
    {
        int n_ = t & 63, rg = t >> 6;
        #pragma unroll
        for (int u16 = 0; u16 < 16; u16++) {
            int u = rg * 16 + u16;      // k4 index 0..63
            float4 v;
            v.x = __ldg(&W[(4 * u + 0) * FOUT + n_]);
            v.y = __ldg(&W[(4 * u + 1) * FOUT + n_]);
            v.z = __ldg(&W[(4 * u + 2) * FOUT + n_]);
            v.w = __ldg(&W[(4 * u + 3) * FOUT + n_]);
            *(float4*)(Wt + n_ * 260 + 4 * u) = v;
        }
    }
    __syncthreads();

    int mt = wid & 3, nh = wid >> 2;
    int g = lane >> 2, tc = lane & 3;
    const float* A0 = hS + (mt * 16 + g) * 260;
    const float* A1 = A0 + 8 * 260;

    float D[4][4];
    #pragma unroll
    for (int nt = 0; nt < 4; nt++) { D[nt][0] = D[nt][1] = D[nt][2] = D[nt][3] = 0.f; }

    #pragma unroll 2
    for (int ks = 0; ks < 32; ks++) {
        int k0 = ks * 8;
        float a00 = A0[k0 + tc],     a10 = A1[k0 + tc];
        float a01 = A0[k0 + tc + 4], a11 = A1[k0 + tc + 4];
        u32 ah0 = tf32cvt(a00), ah1 = tf32cvt(a10), ah2 = tf32cvt(a01), ah3 = tf32cvt(a11);
        u32 al0 = tf32cvt(a00 - __uint_as_float(ah0));
        u32 al1 = tf32cvt(a10 - __uint_as_float(ah1));
        u32 al2 = tf32cvt(a01 - __uint_as_float(ah2));
        u32 al3 = tf32cvt(a11 - __uint_as_float(ah3));
        #pragma unroll
        for (int nt = 0; nt < 4; nt++) {
            const float* B = Wt + (nh * 32 + nt * 8 + g) * 260 + k0;
            float b0f = B[tc], b1f = B[tc + 4];
            u32 bh0 = tf32cvt(b0f), bh1 = tf32cvt(b1f);
            u32 bl0 = tf32cvt(b0f - __uint_as_float(bh0));
            u32 bl1 = tf32cvt(b1f - __uint_as_float(bh1));
            MMAT(D[nt], ah0, ah1, ah2, ah3, bh0, bh1);
            MMAT(D[nt], ah0, ah1, ah2, ah3, bl0, bl1);
            MMAT(D[nt], al0, al1, al2, al3, bh0, bh1);
        }
    }

    // ---- epilogue: split to f16 hi/lo + s1/s2 partials ----
    int r0 = rowBase + mt * 16 + g;
    float p1r0 = 0.f, p2r0 = 0.f, p1r1 = 0.f, p2r1 = 0.f;
    u32* whH32 = (u32*)g_Wh_hi;
    u32* whL32 = (u32*)g_Wh_lo;
    #pragma unroll
    for (int nt = 0; nt < 4; nt++) {
        int n0 = nh * 32 + nt * 8 + tc * 2;
        float a1a = a[n0], a1b = a[n0 + 1];
        float a2a = a[FOUT + n0], a2b = a[FOUT + n0 + 1];
        p1r0 += D[nt][0] * a1a + D[nt][1] * a1b;
        p2r0 += D[nt][0] * a2a + D[nt][1] * a2b;
        p1r1 += D[nt][2] * a1a + D[nt][3] * a1b;
        p2r1 += D[nt][2] * a2a + D[nt][3] * a2b;
        #pragma unroll
        for (int rr = 0; rr < 2; rr++) {
            int row = r0 + rr * 8;
            float v0 = D[nt][rr * 2], v1 = D[nt][rr * 2 + 1];
            __half h0 = __float2half(v0), h1 = __float2half(v1);
            __half l0 = __float2half(v0 - __half2float(h0));
            __half l1 = __float2half(v1 - __half2float(h1));
            __half2 hp = __halves2half2(h0, h1);   // .x = low = n0
            __half2 lp = __halves2half2(l0, l1);
            int ci = row * 32 + nh * 16 + nt * 4 + tc;
            whH32[ci] = *(u32*)&hp;
            whL32[ci] = *(u32*)&lp;
        }
    }
    #pragma unroll
    for (int o = 1; o <= 2; o <<= 1) {
        p1r0 += __shfl_xor_sync(0xffffffffu, p1r0, o);
        p2r0 += __shfl_xor_sync(0xffffffffu, p2r0, o);
        p1r1 += __shfl_xor_sync(0xffffffffu, p1r1, o);
        p2r1 += __shfl_xor_sync(0xffffffffu, p2r1, o);
    }
    if (tc == 0) {
        redS[0][nh][mt * 16 + g]     = p1r0;
        redS[0][nh][mt * 16 + 8 + g] = p1r1;
        redS[1][nh][mt * 16 + g]     = p2r0;
        redS[1][nh][mt * 16 + 8 + g] = p2r1;
    }
    __syncthreads();
    if (t < 64) {
        g_s1[rowBase + t] = redS[0][0][t] + redS[0][1][t];
        g_s2[rowBase + t] = redS[1][0][t] + redS[1][1][t];
    }
}

// ---------------------------------------------------------------------------
// Kernel 2 (v4): mma.sync flash-GAT, 2-pass fp16 split, adj bitmask,
// cp.async double-buffered Wh tiles (no prefetch registers), A-frags for the
// whole subtile precomputed before the MMA loop (16 indep EX2 chains).
// static smem: s2S 8KB + whH 2x9216 + whL 2x9216 = 44.8KB
// ---------------------------------------------------------------------------
__global__ __launch_bounds__(256, 2) void k_main(const int* __restrict__ adj) {
    __shared__ float s2S[JT];
    __shared__ __align__(16) char whH[2 * 9216];
    __shared__ __align__(16) char whL[2 * 9216];

    int t = threadIdx.x, lane = t & 31, wid = t >> 5;
    int blk = blockIdx.x;
    int i0 = (blk >> 2) * RT;
    int jb = (blk & 3) * JT;
    int g = lane >> 2, tc = lane & 3;

    #pragma unroll
    for (int q = 0; q < JT / 256; q++) s2S[t + q * 256] = g_s2[jb + t + q * 256];

    int row0 = i0 + wid * 16 + g;
    float s1v0 = g_s1[row0], s1v1 = g_s1[row0 + 8];
    const int* aR0 = adj + (size_t)row0 * NN + jb;
    const int* aR1 = aR0 + (size_t)8 * NN;

    float D[8][4];
    #pragma unroll
    for (int n = 0; n < 8; n++) { D[n][0] = D[n][1] = D[n][2] = D[n][3] = 0.f; }
    float z0 = 0.f, z1 = 0.f;

    u32 whHb = smem_u32(whH), whLb = smem_u32(whL);
    int laneoff = (((lane >> 3) & 1) * 8 + (lane & 7)) * 144 + (lane >> 4) * 16;

    int sj0 = t >> 3, sc = t & 7;
    const char* gH = (const char*)g_Wh_hi;
    const char* gL = (const char*)g_Wh_lo;

    // issue cp.async group for subtile s into buffer s&1 (4 x 16B per thread)
    auto issueTile = [&](int s) {
        int jn = jb + s * 64;
        const char* sH = gH + ((size_t)(jn + sj0) * 8 + sc) * 16;
        const char* sL = gL + ((size_t)(jn + sj0) * 8 + sc) * 16;
        u32 dH = whHb + (s & 1) * 9216 + sj0 * 144 + sc * 16;
        u32 dL = whLb + (s & 1) * 9216 + sj0 * 144 + sc * 16;
        CPA(dH, sH);  CPA(dH + 32 * 144, sH + 4096);
        CPA(dL, sL);  CPA(dL + 32 * 144, sL + 4096);
    };

    // adj bitmask for subtile s: bit(ks*8 + q*2 + {0,1})
    auto loadBits = [&](int s) -> u32 {
        const int* b0 = aR0 + s * 64;
        const int* b1 = aR1 + s * 64;
        u32 m = 0;
        #pragma unroll
        for (int ks = 0; ks < 4; ks++) {
            int2 v0 = *(const int2*)(b0 + ks * 16 + tc * 2);
            int2 v1 = *(const int2*)(b1 + ks * 16 + tc * 2);
            int2 v2 = *(const int2*)(b0 + ks * 16 + tc * 2 + 8);
            int2 v3 = *(const int2*)(b1 + ks * 16 + tc * 2 + 8);
            u32 base = ks * 8;
            m |= (v0.x > 0 ? 1u : 0u) << (base + 0);
            m |= (v0.y > 0 ? 1u : 0u) << (base + 1);
            m |= (v1.x > 0 ? 1u : 0u) << (base + 2);
            m |= (v1.y > 0 ? 1u : 0u) << (base + 3);
            m |= (v2.x > 0 ? 1u : 0u) << (base + 4);
            m |= (v2.y > 0 ? 1u : 0u) << (base + 5);
            m |= (v3.x > 0 ? 1u : 0u) << (base + 6);
            m |= (v3.y > 0 ? 1u : 0u) << (base + 7);
        }
        return m;
    };

    issueTile(0);
    CPC();
    u32 bC = loadBits(0), bN = 0;

    for (int st = 0; st < NSUB; st++) {
        int bo = (st & 1) * 9216;
        CPW0();             // tile st resident
        __syncthreads();    // all warps done computing st-1 -> buffer (st+1)&1 free

        if (st < NSUB - 1) {
            issueTile(st + 1);
            CPC();
            bN = loadBits(st + 1);
        }

        // ---- A-frags for the whole subtile (16 independent chains) ----
        u32 AH[16];
        #pragma unroll
        for (int ks = 0; ks < 4; ks++) {
            int j0 = ks * 16;
            float2 sa = *(const float2*)&s2S[st * 64 + j0 + tc * 2];
            float2 sb = *(const float2*)&s2S[st * 64 + j0 + tc * 2 + 8];
            #pragma unroll
            for (int q = 0; q < 4; q++) {
                u32 bb = bC >> (ks * 8 + q * 2);
                float s1v  = (q & 1) ? s1v1 : s1v0;
                float2 s2p = (q >> 1) ? sb : sa;
                float x0 = s1v + s2p.x, x1 = s1v + s2p.y;
                float l0 = fmaxf(x0, 0.2f * x0), l1 = fmaxf(x1, 0.2f * x1);
                float e0 = fmaf(l0, 1.44269504f, -8.0f);   // w = exp(lr)*2^-8
                float e1 = fmaf(l1, 1.44269504f, -8.0f);
                e0 = (bb & 1u) ? e0 : -127.0f;
                e1 = (bb & 2u) ? e1 : -127.0f;
                float w0, w1;
                asm("ex2.approx.ftz.f32 %0, %1;" : "=f"(w0) : "f"(e0));
                asm("ex2.approx.ftz.f32 %0, %1;" : "=f"(w1) : "f"(e1));
                if (q & 1) z1 += w0 + w1; else z0 += w0 + w1;
                asm("cvt.rn.satfinite.f16x2.f32 %0, %1, %2;" : "=r"(AH[ks * 4 + q]) : "f"(w1), "f"(w0));
            }
        }

        // ---- MMA loop ----
        #pragma unroll
        for (int ks = 0; ks < 4; ks++) {
            u32* ahi = AH + ks * 4;
            u32 abH = whHb + bo + ks * 16 * 144 + laneoff;
            u32 abL = whLb + bo + ks * 16 * 144 + laneoff;
            #pragma unroll
            for (int nb = 0; nb < 4; nb++) {
                u32 bh0, bh1, bh2, bh3, bl0, bl1, bl2, bl3;
                asm volatile("ldmatrix.sync.aligned.m8n8.x4.trans.shared.b16 {%0,%1,%2,%3}, [%4];"
                    : "=r"(bh0), "=r"(bh1), "=r"(bh2), "=r"(bh3) : "r"(abH + nb * 32));
                asm volatile("ldmatrix.sync.aligned.m8n8.x4.trans.shared.b16 {%0,%1,%2,%3}, [%4];"
                    : "=r"(bl0), "=r"(bl1), "=r"(bl2), "=r"(bl3) : "r"(abL + nb * 32));
                MMA(D[nb * 2],     ahi, bh0, bh1);
                MMA(D[nb * 2],     ahi, bl0, bl1);
                MMA(D[nb * 2 + 1], ahi, bh2, bh3);
                MMA(D[nb * 2 + 1], ahi, bl2, bl3);
            }
        }
        bC = bN;
    }

    // ---- epilogue: Z quad-reduce + partial stores ----
    z0 += __shfl_xor_sync(0xffffffffu, z0, 1);
    z0 += __shfl_xor_sync(0xffffffffu, z0, 2);
    z1 += __shfl_xor_sync(0xffffffffu, z1, 1);
    z1 += __shfl_xor_sync(0xffffffffu, z1, 2);
    if (tc == 0) {
        g_Zp[blk * RT + wid * 16 + g]     = z0;
        g_Zp[blk * RT + wid * 16 + 8 + g] = z1;
    }
    float* db = g_Dp + (size_t)blk * RT * FOUT + (size_t)(wid * 16 + g) * FOUT + tc * 2;
    #pragma unroll
    for (int nt = 0; nt < 8; nt++) {
        *(float2*)(db + nt * 8)             = make_float2(D[nt][0], D[nt][1]);
        *(float2*)(db + 8 * FOUT + nt * 8)  = make_float2(D[nt][2], D[nt][3]);
    }
}

// ---------------------------------------------------------------------------
// Kernel 3: combine 4 j-quarters: out = elu(SumD/SumZ)
// ---------------------------------------------------------------------------
__global__ __launch_bounds__(256) void k_comb(float* __restrict__ out) {
    int idx = blockIdx.x * 256 + threadIdx.x;   // x4 floats
    int i  = idx >> 4;
    int f4 = (idx & 15) * 4;
    int rt = i >> 7, r = i & 127;
    float4 d = make_float4(0.f, 0.f, 0.f, 0.f);
    float z = 0.f;
    #pragma unroll
    for (int p = 0; p < 4; p++) {
        int b = rt * 4 + p;
        const float4 dp = *(const float4*)(g_Dp + (size_t)b * (RT * FOUT) + r * FOUT + f4);
        d.x += dp.x; d.y += dp.y; d.z += dp.z; d.w += dp.w;
        z += g_Zp[b * RT + r];
    }
    float inv = 1.0f / z;
    float v[4] = {d.x * inv, d.y * inv, d.z * inv, d.w * inv};
    #pragma unroll
    for (int c = 0; c < 4; c++) v[c] = (v[c] > 0.f) ? v[c] : expm1f(v[c]);
    *(float4*)(out + (size_t)i * FOUT + f4) = make_float4(v[0], v[1], v[2], v[3]);
}

// ---------------------------------------------------------------------------
extern "C" void kernel_launch(void* const* d_in, const int* in_sizes, int n_in,
                              void* d_out, int out_size) {
    const float* h   = (const float*)d_in[0];
    const int*   adj = (const int*)  d_in[1];
    const float* W   = (const float*)d_in[2];
    const float* a   = (const float*)d_in[3];
    float* out = (float*)d_out;

    cudaFuncSetAttribute(k_prep, cudaFuncAttributeMaxDynamicSharedMemorySize, 133120);
    k_prep<<<NN / 64, 256, 133120>>>(h, W, a);
    k_main<<<NBLK, 256>>>(adj);
    k_comb<<<NN * FOUT / 4 / 256, 256>>>(out);
}

// round 14
// speedup vs baseline: 25.8020x; 1.2326x over previous
#include <cuda_runtime.h>
#include <cuda_fp16.h>
#include <cstdint>

#define NN    8192
#define FIN   256
#define FOUT  64
#define RT    128
#define NBLK  256      // 64 row-tiles x 4 j-quarters
#define JT    2048     // j per block
#define NSUB  32       // subtiles of 64 j

typedef unsigned int u32;

// ---- global scratch (no cudaMalloc allowed) ----
__device__ float g_s1[NN];
__device__ __align__(16) float g_s2[NN];
__device__ __align__(16) __half g_Wh_hi[NN * FOUT];   // [j][f] row-major
__device__ __align__(16) float g_Dp[NBLK * RT * FOUT];
__device__ float g_Zp[NBLK * RT];

static __device__ __forceinline__ u32 smem_u32(const void* p) {
    u32 a;
    asm("{ .reg .u64 t; cvta.to.shared.u64 t, %1; cvt.u32.u64 %0, t; }" : "=r"(a) : "l"(p));
    return a;
}

#define MMA(d, a, b0_, b1_)                                                     \
    asm volatile("mma.sync.aligned.m16n8k16.row.col.f32.f16.f16.f32 "           \
        "{%0,%1,%2,%3}, {%4,%5,%6,%7}, {%8,%9}, {%0,%1,%2,%3};"                 \
        : "+f"(d[0]), "+f"(d[1]), "+f"(d[2]), "+f"(d[3])                        \
        : "r"(a[0]), "r"(a[1]), "r"(a[2]), "r"(a[3]), "r"(b0_), "r"(b1_))

#define MMAT(d, a0_, a1_, a2_, a3_, b0_, b1_)                                   \
    asm volatile("mma.sync.aligned.m16n8k8.row.col.f32.tf32.tf32.f32 "          \
        "{%0,%1,%2,%3}, {%4,%5,%6,%7}, {%8,%9}, {%0,%1,%2,%3};"                 \
        : "+f"(d[0]), "+f"(d[1]), "+f"(d[2]), "+f"(d[3])                        \
        : "r"(a0_), "r"(a1_), "r"(a2_), "r"(a3_), "r"(b0_), "r"(b1_))

static __device__ __forceinline__ u32 tf32cvt(float f) {
    u32 r;
    asm("cvt.rna.tf32.f32 %0, %1;" : "=r"(r) : "f"(f));
    return r;
}

#define CPA(dst, src) asm volatile("cp.async.cg.shared.global [%0], [%1], 16;" :: "r"(dst), "l"(src) : "memory")
#define CPC() asm volatile("cp.async.commit_group;" ::: "memory")
#define CPW0() asm volatile("cp.async.wait_group 0;" ::: "memory")

// ---------------------------------------------------------------------------
// Kernel 1 (v5): Wh = h@W via 3xTF32 MMA; s1/s2; f16 Wh.
// 256 blocks x 32 rows -> 2 blocks/SM (smem 99840B). 8 warps =
// 2 m-tiles x 4 n-quarters (16 n each = 2 ntiles).
// ---------------------------------------------------------------------------
__global__ __launch_bounds__(256, 2) void k_prep(const float* __restrict__ h,
                                                 const float* __restrict__ W,
                                                 const float* __restrict__ a) {
    extern __shared__ float dsm[];
    float* hS = dsm;                    // [32][260]
    float* Wt = dsm + 32 * 260;         // [64][260]  ([n][k])
    __shared__ float redS[2][4][32];
    int t = threadIdx.x, lane = t & 31, wid = t >> 5;
    int rowBase = blockIdx.x * 32;

    // stage h tile (32 x 256 f32)
    const float4* hb4 = (const float4*)(h + (size_t)rowBase * FIN);
    #pragma unroll
    for (int p = 0; p < 8; p++) {
        int idx4 = t + p * 256;
        int r = idx4 >> 6, c4 = idx4 & 63;
        float4 v = hb4[idx4];
        *(float4*)(hS + r * 260 + c4 * 4) = v;
    }
    // stage W transposed [n][k], conflict-free
    {
        int n_ = t & 63, rg = t >> 6;
        #pragma unroll
        for (int u16 = 0; u16 < 16; u16++) {
            int u = rg * 16 + u16;      // k4 index 0..63
            float4 v;
            v.x = __ldg(&W[(4 * u + 0) * FOUT + n_]);
            v.y = __ldg(&W[(4 * u + 1) * FOUT + n_]);
            v.z = __ldg(&W[(4 * u + 2) * FOUT + n_]);
            v.w = __ldg(&W[(4 * u + 3) * FOUT + n_]);
            *(float4*)(Wt + n_ * 260 + 4 * u) = v;
        }
    }
    __syncthreads();

    int mt = wid & 1, nq = wid >> 1;
    int g = lane >> 2, tc = lane & 3;
    const float* A0 = hS + (mt * 16 + g) * 260;
    const float* A1 = A0 + 8 * 260;

    float D[2][4];
    #pragma unroll
    for (int nt = 0; nt < 2; nt++) { D[nt][0] = D[nt][1] = D[nt][2] = D[nt][3] = 0.f; }

    #pragma unroll 4
    for (int ks = 0; ks < 32; ks++) {
        int k0 = ks * 8;
        float a00 = A0[k0 + tc],     a10 = A1[k0 + tc];
        float a01 = A0[k0 + tc + 4], a11 = A1[k0 + tc + 4];
        u32 ah0 = tf32cvt(a00), ah1 = tf32cvt(a10), ah2 = tf32cvt(a01), ah3 = tf32cvt(a11);
        u32 al0 = tf32cvt(a00 - __uint_as_float(ah0));
        u32 al1 = tf32cvt(a10 - __uint_as_float(ah1));
        u32 al2 = tf32cvt(a01 - __uint_as_float(ah2));
        u32 al3 = tf32cvt(a11 - __uint_as_float(ah3));
        #pragma unroll
        for (int nt = 0; nt < 2; nt++) {
            const float* B = Wt + (nq * 16 + nt * 8 + g) * 260 + k0;
            float b0f = B[tc], b1f = B[tc + 4];
            u32 bh0 = tf32cvt(b0f), bh1 = tf32cvt(b1f);
            u32 bl0 = tf32cvt(b0f - __uint_as_float(bh0));
            u32 bl1 = tf32cvt(b1f - __uint_as_float(bh1));
            MMAT(D[nt], ah0, ah1, ah2, ah3, bh0, bh1);
            MMAT(D[nt], ah0, ah1, ah2, ah3, bl0, bl1);
            MMAT(D[nt], al0, al1, al2, al3, bh0, bh1);
        }
    }

    // ---- epilogue: f16 Wh + s1/s2 partials ----
    int r0 = rowBase + mt * 16 + g;
    float p1r0 = 0.f, p2r0 = 0.f, p1r1 = 0.f, p2r1 = 0.f;
    u32* whH32 = (u32*)g_Wh_hi;
    #pragma unroll
    for (int nt = 0; nt < 2; nt++) {
        int n0 = nq * 16 + nt * 8 + tc * 2;
        float a1a = a[n0], a1b = a[n0 + 1];
        float a2a = a[FOUT + n0], a2b = a[FOUT + n0 + 1];
        p1r0 += D[nt][0] * a1a + D[nt][1] * a1b;
        p2r0 += D[nt][0] * a2a + D[nt][1] * a2b;
        p1r1 += D[nt][2] * a1a + D[nt][3] * a1b;
        p2r1 += D[nt][2] * a2a + D[nt][3] * a2b;
        #pragma unroll
        for (int rr = 0; rr < 2; rr++) {
            int row = r0 + rr * 8;
            __half2 hp = __halves2half2(__float2half(D[nt][rr * 2]),
                                        __float2half(D[nt][rr * 2 + 1]));
            whH32[row * 32 + nq * 8 + nt * 4 + tc] = *(u32*)&hp;
        }
    }
    #pragma unroll
    for (int o = 1; o <= 2; o <<= 1) {
        p1r0 += __shfl_xor_sync(0xffffffffu, p1r0, o);
        p2r0 += __shfl_xor_sync(0xffffffffu, p2r0, o);
        p1r1 += __shfl_xor_sync(0xffffffffu, p1r1, o);
        p2r1 += __shfl_xor_sync(0xffffffffu, p2r1, o);
    }
    if (tc == 0) {
        redS[0][nq][mt * 16 + g]     = p1r0;
        redS[0][nq][mt * 16 + 8 + g] = p1r1;
        redS[1][nq][mt * 16 + g]     = p2r0;
        redS[1][nq][mt * 16 + 8 + g] = p2r1;
    }
    __syncthreads();
    if (t < 32) {
        g_s1[rowBase + t] = (redS[0][0][t] + redS[0][1][t]) + (redS[0][2][t] + redS[0][3][t]);
        g_s2[rowBase + t] = (redS[1][0][t] + redS[1][1][t]) + (redS[1][2][t] + redS[1][3][t]);
    }
}

// ---------------------------------------------------------------------------
// Kernel 2 (v5): mma.sync flash-GAT, SINGLE-pass pure f16 (A & B splits both
// dropped; measured per-source error contribution ~4e-5 after softmax-sum
// averaging -> total ~1e-4, 10x under gate). Halves HMMA/LDSM/cp.async.
// static smem: s2S 8KB + whH 2x9216 = 26.4KB
// ---------------------------------------------------------------------------
__global__ __launch_bounds__(256, 2) void k_main(const int* __restrict__ adj) {
    __shared__ float s2S[JT];
    __shared__ __align__(16) char whH[2 * 9216];

    int t = threadIdx.x, lane = t & 31, wid = t >> 5;
    int blk = blockIdx.x;
    int i0 = (blk >> 2) * RT;
    int jb = (blk & 3) * JT;
    int g = lane >> 2, tc = lane & 3;

    #pragma unroll
    for (int q = 0; q < JT / 256; q++) s2S[t + q * 256] = g_s2[jb + t + q * 256];

    int row0 = i0 + wid * 16 + g;
    float s1v0 = g_s1[row0], s1v1 = g_s1[row0 + 8];
    const int* aR0 = adj + (size_t)row0 * NN + jb;
    const int* aR1 = aR0 + (size_t)8 * NN;

    float D[8][4];
    #pragma unroll
    for (int n = 0; n < 8; n++) { D[n][0] = D[n][1] = D[n][2] = D[n][3] = 0.f; }
    float z0 = 0.f, z1 = 0.f;

    u32 whHb = smem_u32(whH);
    int laneoff = (((lane >> 3) & 1) * 8 + (lane & 7)) * 144 + (lane >> 4) * 16;

    int sj0 = t >> 3, sc = t & 7;
    const char* gH = (const char*)g_Wh_hi;

    auto issueTile = [&](int s) {
        int jn = jb + s * 64;
        const char* sH = gH + ((size_t)(jn + sj0) * 8 + sc) * 16;
        u32 dH = whHb + (s & 1) * 9216 + sj0 * 144 + sc * 16;
        CPA(dH, sH);  CPA(dH + 32 * 144, sH + 4096);
    };

    auto loadBits = [&](int s) -> u32 {
        const int* b0 = aR0 + s * 64;
        const int* b1 = aR1 + s * 64;
        u32 m = 0;
        #pragma unroll
        for (int ks = 0; ks < 4; ks++) {
            int2 v0 = *(const int2*)(b0 + ks * 16 + tc * 2);
            int2 v1 = *(const int2*)(b1 + ks * 16 + tc * 2);
            int2 v2 = *(const int2*)(b0 + ks * 16 + tc * 2 + 8);
            int2 v3 = *(const int2*)(b1 + ks * 16 + tc * 2 + 8);
            u32 base = ks * 8;
            m |= (v0.x > 0 ? 1u : 0u) << (base + 0);
            m |= (v0.y > 0 ? 1u : 0u) << (base + 1);
            m |= (v1.x > 0 ? 1u : 0u) << (base + 2);
            m |= (v1.y > 0 ? 1u : 0u) << (base + 3);
            m |= (v2.x > 0 ? 1u : 0u) << (base + 4);
            m |= (v2.y > 0 ? 1u : 0u) << (base + 5);
            m |= (v3.x > 0 ? 1u : 0u) << (base + 6);
            m |= (v3.y > 0 ? 1u : 0u) << (base + 7);
        }
        return m;
    };

    issueTile(0);
    CPC();
    u32 bC = loadBits(0), bN = 0;

    for (int st = 0; st < NSUB; st++) {
        int bo = (st & 1) * 9216;
        CPW0();             // tile st resident
        __syncthreads();    // all warps done with buffer (st+1)&1

        if (st < NSUB - 1) {
            issueTile(st + 1);
            CPC();
            bN = loadBits(st + 1);
        }

        // ---- A-frags for the whole subtile (16 independent chains) ----
        u32 AH[16];
        #pragma unroll
        for (int ks = 0; ks < 4; ks++) {
            int j0 = ks * 16;
            float2 sa = *(const float2*)&s2S[st * 64 + j0 + tc * 2];
            float2 sb = *(const float2*)&s2S[st * 64 + j0 + tc * 2 + 8];
            #pragma unroll
            for (int q = 0; q < 4; q++) {
                u32 bb = bC >> (ks * 8 + q * 2);
                float s1v  = (q & 1) ? s1v1 : s1v0;
                float2 s2p = (q >> 1) ? sb : sa;
                float x0 = s1v + s2p.x, x1 = s1v + s2p.y;
                float l0 = fmaxf(x0, 0.2f * x0), l1 = fmaxf(x1, 0.2f * x1);
                float e0 = fmaf(l0, 1.44269504f, -8.0f);   // w = exp(lr)*2^-8
                float e1 = fmaf(l1, 1.44269504f, -8.0f);
                e0 = (bb & 1u) ? e0 : -127.0f;
                e1 = (bb & 2u) ? e1 : -127.0f;
                float w0, w1;
                asm("ex2.approx.ftz.f32 %0, %1;" : "=f"(w0) : "f"(e0));
                asm("ex2.approx.ftz.f32 %0, %1;" : "=f"(w1) : "f"(e1));
                if (q & 1) z1 += w0 + w1; else z0 += w0 + w1;
                asm("cvt.rn.satfinite.f16x2.f32 %0, %1, %2;" : "=r"(AH[ks * 4 + q]) : "f"(w1), "f"(w0));
            }
        }

        // ---- MMA loop (single pass) ----
        #pragma unroll
        for (int ks = 0; ks < 4; ks++) {
            u32* ahi = AH + ks * 4;
            u32 abH = whHb + bo + ks * 16 * 144 + laneoff;
            #pragma unroll
            for (int nb = 0; nb < 4; nb++) {
                u32 bh0, bh1, bh2, bh3;
                asm volatile("ldmatrix.sync.aligned.m8n8.x4.trans.shared.b16 {%0,%1,%2,%3}, [%4];"
                    : "=r"(bh0), "=r"(bh1), "=r"(bh2), "=r"(bh3) : "r"(abH + nb * 32));
                MMA(D[nb * 2],     ahi, bh0, bh1);
                MMA(D[nb * 2 + 1], ahi, bh2, bh3);
            }
        }
        bC = bN;
    }

    // ---- epilogue: Z quad-reduce + partial stores ----
    z0 += __shfl_xor_sync(0xffffffffu, z0, 1);
    z0 += __shfl_xor_sync(0xffffffffu, z0, 2);
    z1 += __shfl_xor_sync(0xffffffffu, z1, 1);
    z1 += __shfl_xor_sync(0xffffffffu, z1, 2);
    if (tc == 0) {
        g_Zp[blk * RT + wid * 16 + g]     = z0;
        g_Zp[blk * RT + wid * 16 + 8 + g] = z1;
    }
    float* db = g_Dp + (size_t)blk * RT * FOUT + (size_t)(wid * 16 + g) * FOUT + tc * 2;
    #pragma unroll
    for (int nt = 0; nt < 8; nt++) {
        *(float2*)(db + nt * 8)             = make_float2(D[nt][0], D[nt][1]);
        *(float2*)(db + 8 * FOUT + nt * 8)  = make_float2(D[nt][2], D[nt][3]);
    }
}

// ---------------------------------------------------------------------------
// Kernel 3: combine 4 j-quarters: out = elu(SumD/SumZ)
// ---------------------------------------------------------------------------
__global__ __launch_bounds__(256) void k_comb(float* __restrict__ out) {
    int idx = blockIdx.x * 256 + threadIdx.x;   // x4 floats
    int i  = idx >> 4;
    int f4 = (idx & 15) * 4;
    int rt = i >> 7, r = i & 127;
    float4 d = make_float4(0.f, 0.f, 0.f, 0.f);
    float z = 0.f;
    #pragma unroll
    for (int p = 0; p < 4; p++) {
        int b = rt * 4 + p;
        const float4 dp = *(const float4*)(g_Dp + (size_t)b * (RT * FOUT) + r * FOUT + f4);
        d.x += dp.x; d.y += dp.y; d.z += dp.z; d.w += dp.w;
        z += g_Zp[b * RT + r];
    }
    float inv = 1.0f / z;
    float v[4] = {d.x * inv, d.y * inv, d.z * inv, d.w * inv};
    #pragma unroll
    for (int c = 0; c < 4; c++) v[c] = (v[c] > 0.f) ? v[c] : expm1f(v[c]);
    *(float4*)(out + (size_t)i * FOUT + f4) = make_float4(v[0], v[1], v[2], v[3]);
}

// ---------------------------------------------------------------------------
extern "C" void kernel_launch(void* const* d_in, const int* in_sizes, int n_in,
                              void* d_out, int out_size) {
    const float* h   = (const float*)d_in[0];
    const int*   adj = (const int*)  d_in[1];
    const float* W   = (const float*)d_in[2];
    const float* a   = (const float*)d_in[3];
    float* out = (float*)d_out;

    cudaFuncSetAttribute(k_prep, cudaFuncAttributeMaxDynamicSharedMemorySize, 99840);
    k_prep<<<NN / 32, 256, 99840>>>(h, W, a);
    k_main<<<NBLK, 256>>>(adj);
    k_comb<<<NN * FOUT / 4 / 256, 256>>>(out);
}